// round 15
// baseline (speedup 1.0000x reference)
#include <cuda_runtime.h>
#include <math.h>

#define Nn 30000
#define Ee 480000
#define Hh 128
#define NHh 4
#define Gg 64
#define EPSf 1e-5f
#define NT64 469   // ceil(30000/64)

typedef unsigned long long ull;
union U2 { float4 f; struct { ull lo, hi; } u; };

__device__ __forceinline__ ull pk2(float x, float y) {
    ull r; asm("mov.b64 %0,{%1,%2};" : "=l"(r) : "f"(x), "f"(y)); return r;
}
__device__ __forceinline__ ull f2(ull a, ull b, ull c) {
    ull d; asm("fma.rn.f32x2 %0,%1,%2,%3;" : "=l"(d) : "l"(a), "l"(b), "l"(c)); return d;
}
__device__ __forceinline__ float2 up2(ull v) {
    float2 f; asm("mov.b64 {%0,%1},%2;" : "=f"(f.x), "=f"(f.y) : "l"(v)); return f;
}
__device__ __forceinline__ void red4(float* p, float4 v) {
    asm volatile("red.global.add.v4.f32 [%0],{%1,%2,%3,%4};"
                 :: "l"(p), "f"(v.x), "f"(v.y), "f"(v.z), "f"(v.w) : "memory");
}
__device__ __forceinline__ void red1(float* p, float v) {
    asm volatile("red.global.add.f32 [%0],%1;" :: "l"(p), "f"(v) : "memory");
}

// ---------------- scratch (device globals) ----------------
__device__ float g_src[Nn*Hh];
__device__ float g_dst[Nn*Hh];
__device__ float g_val[Nn*Hh];
__device__ float g_scores[(size_t)Ee*NHh];
__device__ float g_smax[Nn*NHh];
__device__ float g_den[Nn*NHh];
__device__ float g_numer[Nn*Hh];
__device__ float g_nodenew[Nn*Hh];
__device__ float g_gate[Nn*Hh];
__device__ float g_h1[Nn*Hh];
__device__ float g_h2[Nn*Hh];
// [0,GH) sum1 | [GH,2GH) sq1 | [2GH,3GH) sum2 | [3GH,4GH) sq2 | [4GH,4GH+G) cnt
__device__ float g_stats[4*Gg*Hh + Gg];

// load half of a 128x128 B (64 K-rows) de-interleaved into Bs (2048 float4)
__device__ __forceinline__ void load_Bhalf(float4* Bs4, const float4* B4half, int tid) {
#pragma unroll
    for (int it = 0; it < 8; it++) {
        int v = tid + 256*it;
        int c4 = v & 31;
        Bs4[(v & ~31) | (((c4 & 1) << 4) | (c4 >> 1))] = B4half[v];
    }
}

// combined-weight B-half loader: z = Wa + sgn*Wb (for gate's Wg1/Wg2)
__device__ __forceinline__ void load_Bhalf_comb(float4* Bs4, const float4* Wa,
                                                const float4* Wb, float sgn, int tid) {
#pragma unroll
    for (int it = 0; it < 8; it++) {
        int v = tid + 256*it;
        int c4 = v & 31;
        float4 x = Wa[v], y = Wb[v];
        float4 z = make_float4(x.x + sgn*y.x, x.y + sgn*y.y, x.z + sgn*y.z, x.w + sgn*y.w);
        Bs4[(v & ~31) | (((c4 & 1) << 4) | (c4 >> 1))] = z;
    }
}

// ======== 8-row inner loop (edge_fused only) ========
__device__ __forceinline__ void gemm_half(ull acc[8][4], const float4* Bs4, const float4* As4,
                                          int k4_0, int cg, int r0) {
    for (int k4 = k4_0; k4 < k4_0 + 16; k4++) {
        float4 a4[8];
#pragma unroll
        for (int rr = 0; rr < 8; rr++) a4[rr] = As4[(r0 + rr)*33 + k4];
#pragma unroll
        for (int kk = 0; kk < 4; kk++) {
            U2 w0, w1;
            w0.f = Bs4[((k4 - k4_0)*4 + kk)*32 + cg];
            w1.f = Bs4[((k4 - k4_0)*4 + kk)*32 + 16 + cg];
#pragma unroll
            for (int rr = 0; rr < 8; rr++) {
                float a = ((float*)&a4[rr])[kk];
                ull pa = pk2(a, a);
                acc[rr][0] = f2(pa, w0.u.lo, acc[rr][0]);
                acc[rr][1] = f2(pa, w0.u.hi, acc[rr][1]);
                acc[rr][2] = f2(pa, w1.u.lo, acc[rr][2]);
                acc[rr][3] = f2(pa, w1.u.hi, acc[rr][3]);
            }
        }
    }
}

// ======== 4-row inner loop (node-side 64-row tiles) ========
__device__ __forceinline__ void gemm_half4(ull acc[4][4], const float4* Bs4, const float4* As4,
                                           int k4_0, int cg, int r0) {
    for (int k4 = k4_0; k4 < k4_0 + 16; k4++) {
        float4 a4[4];
#pragma unroll
        for (int rr = 0; rr < 4; rr++) a4[rr] = As4[(r0 + rr)*33 + k4];
#pragma unroll
        for (int kk = 0; kk < 4; kk++) {
            U2 w0, w1;
            w0.f = Bs4[((k4 - k4_0)*4 + kk)*32 + cg];
            w1.f = Bs4[((k4 - k4_0)*4 + kk)*32 + 16 + cg];
#pragma unroll
            for (int rr = 0; rr < 4; rr++) {
                float a = ((float*)&a4[rr])[kk];
                ull pa = pk2(a, a);
                acc[rr][0] = f2(pa, w0.u.lo, acc[rr][0]);
                acc[rr][1] = f2(pa, w0.u.hi, acc[rr][1]);
                acc[rr][2] = f2(pa, w1.u.lo, acc[rr][2]);
                acc[rr][3] = f2(pa, w1.u.hi, acc[rr][3]);
            }
        }
    }
}

// 64-row A tile loader
__device__ __forceinline__ void load_Atile64(float4* As4, const float4* A4, int row0, int tid) {
#pragma unroll
    for (int it = 0; it < 8; it++) {
        int v = tid + 256*it;
        int r = v >> 5, q = v & 31;
        As4[r*33 + q] = (row0 + r < Nn) ? A4[(size_t)(row0 + r)*32 + q]
                                        : make_float4(0.f,0.f,0.f,0.f);
    }
}

// GraphNorm on a float4 (must match everywhere for consistency)
__device__ __forceinline__ float4 gnorm4(float4 x, float4 s1, float4 s2, float rc,
                                         float4 a, float4 w, float4 bb) {
    float4 y;
    {
        float mean = s1.x*rc, m2 = s2.x*rc;
        float var = m2 + mean*mean*(a.x*a.x - 2.f*a.x);
        y.x = w.x * (x.x - a.x*mean) * rsqrtf(var + EPSf) + bb.x;
    }
    {
        float mean = s1.y*rc, m2 = s2.y*rc;
        float var = m2 + mean*mean*(a.y*a.y - 2.f*a.y);
        y.y = w.y * (x.y - a.y*mean) * rsqrtf(var + EPSf) + bb.y;
    }
    {
        float mean = s1.z*rc, m2 = s2.z*rc;
        float var = m2 + mean*mean*(a.z*a.z - 2.f*a.z);
        y.z = w.z * (x.z - a.z*mean) * rsqrtf(var + EPSf) + bb.z;
    }
    {
        float mean = s1.w*rc, m2 = s2.w*rc;
        float var = m2 + mean*mean*(a.w*a.w - 2.f*a.w);
        y.w = w.w * (x.w - a.w*mean) * rsqrtf(var + EPSf) + bb.w;
    }
    return y;
}

// ============ projection: task = (tile64, weight); grid = 3*NT64 ============
__global__ __launch_bounds__(256, 3) void gemm_proj(
        const float* __restrict__ A,
        const float* __restrict__ B0, const float* __restrict__ b0, float* __restrict__ C0,
        const float* __restrict__ B1, const float* __restrict__ b1, float* __restrict__ C1,
        const float* __restrict__ B2, const float* __restrict__ b2, float* __restrict__ C2) {
    extern __shared__ float sm[];
    float4* Bs4 = (float4*)sm;
    float4* As4 = (float4*)(sm + 8192);
    int tid = threadIdx.x;
    int w = blockIdx.x / NT64;
    int row0 = (blockIdx.x % NT64) * 64;
    const float* B = (w == 0) ? B0 : (w == 1) ? B1 : B2;
    const float* bias = (w == 0) ? b0 : (w == 1) ? b1 : b2;
    float* C = (w == 0) ? C0 : (w == 1) ? C1 : C2;

    load_Atile64(As4, (const float4*)A, row0, tid);
    const float4* B4 = (const float4*)B;
    load_Bhalf(Bs4, B4, tid);
    __syncthreads();
    int rg = tid >> 4, cg = tid & 15;
    int r0 = rg * 4;
    ull acc[4][4];
#pragma unroll
    for (int rr = 0; rr < 4; rr++) { acc[rr][0]=0; acc[rr][1]=0; acc[rr][2]=0; acc[rr][3]=0; }
    gemm_half4(acc, Bs4, As4, 0, cg, r0);
    __syncthreads();
    load_Bhalf(Bs4, B4 + 2048, tid);
    __syncthreads();
    gemm_half4(acc, Bs4, As4, 16, cg, r0);
    float4 bi0 = ((const float4*)bias)[cg*2];
    float4 bi1 = ((const float4*)bias)[cg*2 + 1];
#pragma unroll
    for (int rr = 0; rr < 4; rr++) {
        int r = row0 + r0 + rr;
        if (r < Nn) {
            float2 f0 = up2(acc[rr][0]), f1 = up2(acc[rr][1]);
            float2 f2_ = up2(acc[rr][2]), f3 = up2(acc[rr][3]);
            ((float4*)C)[(size_t)r*32 + cg*2]     = make_float4(f0.x+bi0.x, f0.y+bi0.y, f1.x+bi0.z, f1.y+bi0.w);
            ((float4*)C)[(size_t)r*32 + cg*2 + 1] = make_float4(f2_.x+bi1.x, f2_.y+bi1.y, f3.x+bi1.z, f3.y+bi1.w);
        }
    }
}

// ============ merged: nodenew GEMM + gate (2 GEMMs) + sigmoid + h1 + stats1 (64-row) ============
__global__ __launch_bounds__(256, 3) void gemm_nngate(
        const float* __restrict__ node,
        const float* __restrict__ Wun, const float* __restrict__ bun,
        const float* __restrict__ Wg,  const float* __restrict__ bg,
        const int* __restrict__ batch) {
    extern __shared__ float sm[];
    float4* Bs4 = (float4*)sm;
    float4* As4 = (float4*)(sm + 8192);
    int tid = threadIdx.x;
    int row0 = blockIdx.x * 64;
    int rg = tid >> 4, cg = tid & 15;
    int r0 = rg * 4;
    const float4* Wg4 = (const float4*)Wg;

    // ---- PHASE A: nodenew = (numer/den)@Wun + bun ----
#pragma unroll
    for (int it = 0; it < 8; it++) {
        int v = tid + 256*it;
        int r = v >> 5, q = v & 31;
        float4 x = make_float4(0.f,0.f,0.f,0.f);
        int row = row0 + r;
        if (row < Nn) {
            x = ((const float4*)g_numer)[(size_t)row*32 + q];
            float dv = g_den[row*4 + (q >> 3)];
            float inv = (dv > 0.f) ? __fdividef(1.f, dv) : 0.f;
            x.x *= inv; x.y *= inv; x.z *= inv; x.w *= inv;
        }
        As4[r*33 + q] = x;
    }
    ull acc[4][4];
#pragma unroll
    for (int rr = 0; rr < 4; rr++) { acc[rr][0]=0; acc[rr][1]=0; acc[rr][2]=0; acc[rr][3]=0; }
    load_Bhalf(Bs4, (const float4*)Wun, tid);
    __syncthreads();
    gemm_half4(acc, Bs4, As4, 0, cg, r0);
    __syncthreads();
    load_Bhalf(Bs4, (const float4*)Wun + 2048, tid);
    __syncthreads();
    gemm_half4(acc, Bs4, As4, 16, cg, r0);
    __syncthreads();   // all reads of numer tile done
    {
        float4 bi0 = ((const float4*)bun)[cg*2];
        float4 bi1 = ((const float4*)bun)[cg*2 + 1];
#pragma unroll
        for (int rr = 0; rr < 4; rr++) {
            int r = row0 + r0 + rr;
            float2 f0 = up2(acc[rr][0]), f1 = up2(acc[rr][1]);
            float2 f2_ = up2(acc[rr][2]), f3 = up2(acc[rr][3]);
            float4 v0 = make_float4(f0.x+bi0.x, f0.y+bi0.y, f1.x+bi0.z, f1.y+bi0.w);
            float4 v1 = make_float4(f2_.x+bi1.x, f2_.y+bi1.y, f3.x+bi1.z, f3.y+bi1.w);
            As4[(r0 + rr)*33 + cg*2]     = v0;
            As4[(r0 + rr)*33 + cg*2 + 1] = v1;
            if (r < Nn) {
                ((float4*)g_nodenew)[(size_t)r*32 + cg*2]     = v0;
                ((float4*)g_nodenew)[(size_t)r*32 + cg*2 + 1] = v1;
            }
        }
    }
    __syncthreads();

    // ---- PHASE B: accG = nodenew(As) @ (Wg[0:H] + Wg[2H:3H]) ----
#pragma unroll
    for (int rr = 0; rr < 4; rr++) { acc[rr][0]=0; acc[rr][1]=0; acc[rr][2]=0; acc[rr][3]=0; }
    load_Bhalf_comb(Bs4, Wg4, Wg4 + 8192, 1.f, tid);
    __syncthreads();
    gemm_half4(acc, Bs4, As4, 0, cg, r0);
    __syncthreads();
    load_Bhalf_comb(Bs4, Wg4 + 2048, Wg4 + 8192 + 2048, 1.f, tid);
    __syncthreads();
    gemm_half4(acc, Bs4, As4, 16, cg, r0);
    __syncthreads();

    // ---- PHASE C: accG += node @ (Wg[H:2H] - Wg[2H:3H]) ----
    load_Atile64(As4, (const float4*)node, row0, tid);
    load_Bhalf_comb(Bs4, Wg4 + 4096, Wg4 + 8192, -1.f, tid);
    __syncthreads();
    gemm_half4(acc, Bs4, As4, 0, cg, r0);
    __syncthreads();
    load_Bhalf_comb(Bs4, Wg4 + 4096 + 2048, Wg4 + 8192 + 2048, -1.f, tid);
    __syncthreads();
    gemm_half4(acc, Bs4, As4, 16, cg, r0);

    // ---- EPILOGUE: gate, h1, stats (node read from As; nodenew from g_nodenew/L2) ----
    float4 bi0 = ((const float4*)bg)[cg*2];
    float4 bi1 = ((const float4*)bg)[cg*2 + 1];
#pragma unroll
    for (int rr = 0; rr < 4; rr++) {
        int r = row0 + r0 + rr;
        if (r < Nn) {
            float2 f0 = up2(acc[rr][0]), f1 = up2(acc[rr][1]);
            float2 f2_ = up2(acc[rr][2]), f3 = up2(acc[rr][3]);
            float4 v0 = make_float4(f0.x+bi0.x, f0.y+bi0.y, f1.x+bi0.z, f1.y+bi0.w);
            float4 v1 = make_float4(f2_.x+bi1.x, f2_.y+bi1.y, f3.x+bi1.z, f3.y+bi1.w);
            v0.x = 1.f/(1.f+expf(-v0.x)); v0.y = 1.f/(1.f+expf(-v0.y));
            v0.z = 1.f/(1.f+expf(-v0.z)); v0.w = 1.f/(1.f+expf(-v0.w));
            v1.x = 1.f/(1.f+expf(-v1.x)); v1.y = 1.f/(1.f+expf(-v1.y));
            v1.z = 1.f/(1.f+expf(-v1.z)); v1.w = 1.f/(1.f+expf(-v1.w));
            ((float4*)g_gate)[(size_t)r*32 + cg*2]     = v0;
            ((float4*)g_gate)[(size_t)r*32 + cg*2 + 1] = v1;
            float4 nn0 = ((const float4*)g_nodenew)[(size_t)r*32 + cg*2];
            float4 nn1 = ((const float4*)g_nodenew)[(size_t)r*32 + cg*2 + 1];
            float4 nd0 = As4[(r0 + rr)*33 + cg*2];       // node tile still resident
            float4 nd1 = As4[(r0 + rr)*33 + cg*2 + 1];
            float4 h0 = make_float4(v0.x*nn0.x+nd0.x, v0.y*nn0.y+nd0.y,
                                    v0.z*nn0.z+nd0.z, v0.w*nn0.w+nd0.w);
            float4 h1v = make_float4(v1.x*nn1.x+nd1.x, v1.y*nn1.y+nd1.y,
                                     v1.z*nn1.z+nd1.z, v1.w*nn1.w+nd1.w);
            ((float4*)g_h1)[(size_t)r*32 + cg*2]     = h0;
            ((float4*)g_h1)[(size_t)r*32 + cg*2 + 1] = h1v;
            int b = batch[r];
            red4(&g_stats[b*Hh + cg*8],     h0);
            red4(&g_stats[b*Hh + cg*8 + 4], h1v);
            red4(&g_stats[Gg*Hh + b*Hh + cg*8],
                 make_float4(h0.x*h0.x, h0.y*h0.y, h0.z*h0.z, h0.w*h0.w));
            red4(&g_stats[Gg*Hh + b*Hh + cg*8 + 4],
                 make_float4(h1v.x*h1v.x, h1v.y*h1v.y, h1v.z*h1v.z, h1v.w*h1v.w));
            if (cg == 0) red1(&g_stats[4*Gg*Hh + b], 1.f);
        }
    }
}

// ============ fused fix_node with inline norm1 (64-row tiles) ============
__global__ __launch_bounds__(256, 3) void gemm_fix_h2(
        const float* __restrict__ Wf1, const float* __restrict__ bf1,
        const float* __restrict__ Wf2, const float* __restrict__ bf2,
        const float* __restrict__ gn1w, const float* __restrict__ gn1b,
        const float* __restrict__ gn1a, const int* __restrict__ batch) {
    extern __shared__ float sm[];
    float4* Bs4 = (float4*)sm;
    float4* As4 = (float4*)(sm + 8192);
    int tid = threadIdx.x;
    int row0 = blockIdx.x * 64;
    int rg = tid >> 4, cg = tid & 15;
    int r0 = rg * 4;

#pragma unroll
    for (int it = 0; it < 8; it++) {
        int v = tid + 256*it;
        int r = v >> 5, q = v & 31;
        int row = row0 + r;
        float4 x = make_float4(0.f,0.f,0.f,0.f);
        if (row < Nn) {
            x = ((const float4*)g_h1)[(size_t)row*32 + q];
            int b = batch[row];
            float rc = 1.f / fmaxf(g_stats[4*Gg*Hh + b], 1.f);
            float4 s1 = *(const float4*)&g_stats[b*Hh + q*4];
            float4 s2 = *(const float4*)&g_stats[Gg*Hh + b*Hh + q*4];
            x = gnorm4(x, s1, s2, rc,
                       ((const float4*)gn1a)[q], ((const float4*)gn1w)[q],
                       ((const float4*)gn1b)[q]);
        }
        As4[r*33 + q] = x;
    }
    ull acc[4][4];
#pragma unroll
    for (int rr = 0; rr < 4; rr++) { acc[rr][0]=0; acc[rr][1]=0; acc[rr][2]=0; acc[rr][3]=0; }
    load_Bhalf(Bs4, (const float4*)Wf1, tid);
    __syncthreads();
    gemm_half4(acc, Bs4, As4, 0, cg, r0);
    __syncthreads();
    load_Bhalf(Bs4, (const float4*)Wf1 + 2048, tid);
    __syncthreads();
    gemm_half4(acc, Bs4, As4, 16, cg, r0);
    __syncthreads();
    {
        float4 bi0 = ((const float4*)bf1)[cg*2];
        float4 bi1 = ((const float4*)bf1)[cg*2 + 1];
#pragma unroll
        for (int rr = 0; rr < 4; rr++) {
            float2 f0 = up2(acc[rr][0]), f1 = up2(acc[rr][1]);
            float2 f2_ = up2(acc[rr][2]), f3 = up2(acc[rr][3]);
            float v[8] = { f0.x+bi0.x, f0.y+bi0.y, f1.x+bi0.z, f1.y+bi0.w,
                           f2_.x+bi1.x, f2_.y+bi1.y, f3.x+bi1.z, f3.y+bi1.w };
#pragma unroll
            for (int q = 0; q < 8; q++) v[q] = v[q] > 0.f ? v[q] : 0.01f*v[q];
            As4[(r0 + rr)*33 + cg*2]     = make_float4(v[0], v[1], v[2], v[3]);
            As4[(r0 + rr)*33 + cg*2 + 1] = make_float4(v[4], v[5], v[6], v[7]);
        }
    }
    __syncthreads();
#pragma unroll
    for (int rr = 0; rr < 4; rr++) { acc[rr][0]=0; acc[rr][1]=0; acc[rr][2]=0; acc[rr][3]=0; }
    load_Bhalf(Bs4, (const float4*)Wf2, tid);
    __syncthreads();
    gemm_half4(acc, Bs4, As4, 0, cg, r0);
    __syncthreads();
    load_Bhalf(Bs4, (const float4*)Wf2 + 2048, tid);
    __syncthreads();
    gemm_half4(acc, Bs4, As4, 16, cg, r0);

    float4 bi0 = ((const float4*)bf2)[cg*2];
    float4 bi1 = ((const float4*)bf2)[cg*2 + 1];
#pragma unroll
    for (int rr = 0; rr < 4; rr++) {
        int r = row0 + r0 + rr;
        if (r < Nn) {
            float2 f0 = up2(acc[rr][0]), f1 = up2(acc[rr][1]);
            float2 f2_ = up2(acc[rr][2]), f3 = up2(acc[rr][3]);
            float4 x0 = make_float4(f0.x+bi0.x, f0.y+bi0.y, f1.x+bi0.z, f1.y+bi0.w);
            float4 x1 = make_float4(f2_.x+bi1.x, f2_.y+bi1.y, f3.x+bi1.z, f3.y+bi1.w);
            int b = batch[r];
            float rc = 1.f / fmaxf(g_stats[4*Gg*Hh + b], 1.f);
            int q0 = cg*2, q1 = cg*2 + 1;
            float4 h1a = ((const float4*)g_h1)[(size_t)r*32 + q0];
            float4 h1b = ((const float4*)g_h1)[(size_t)r*32 + q1];
            float4 n10 = gnorm4(h1a, *(const float4*)&g_stats[b*Hh + q0*4],
                                *(const float4*)&g_stats[Gg*Hh + b*Hh + q0*4], rc,
                                ((const float4*)gn1a)[q0], ((const float4*)gn1w)[q0],
                                ((const float4*)gn1b)[q0]);
            float4 n11 = gnorm4(h1b, *(const float4*)&g_stats[b*Hh + q1*4],
                                *(const float4*)&g_stats[Gg*Hh + b*Hh + q1*4], rc,
                                ((const float4*)gn1a)[q1], ((const float4*)gn1w)[q1],
                                ((const float4*)gn1b)[q1]);
            float4 gg0 = ((const float4*)g_gate)[(size_t)r*32 + q0];
            float4 gg1 = ((const float4*)g_gate)[(size_t)r*32 + q1];
            float4 h0 = make_float4(gg0.x*x0.x+n10.x, gg0.y*x0.y+n10.y,
                                    gg0.z*x0.z+n10.z, gg0.w*x0.w+n10.w);
            float4 h1v = make_float4(gg1.x*x1.x+n11.x, gg1.y*x1.y+n11.y,
                                     gg1.z*x1.z+n11.z, gg1.w*x1.w+n11.w);
            ((float4*)g_h2)[(size_t)r*32 + q0] = h0;
            ((float4*)g_h2)[(size_t)r*32 + q1] = h1v;
            red4(&g_stats[2*Gg*Hh + b*Hh + cg*8],     h0);
            red4(&g_stats[2*Gg*Hh + b*Hh + cg*8 + 4], h1v);
            red4(&g_stats[3*Gg*Hh + b*Hh + cg*8],
                 make_float4(h0.x*h0.x, h0.y*h0.y, h0.z*h0.z, h0.w*h0.w));
            red4(&g_stats[3*Gg*Hh + b*Hh + cg*8 + 4],
                 make_float4(h1v.x*h1v.x, h1v.y*h1v.y, h1v.z*h1v.z, h1v.w*h1v.w));
        }
    }
}

// ============ fused edge kernel (UNCHANGED) ============
__global__ __launch_bounds__(256, 2) void edge_fused(
        const float* __restrict__ edge, const float* __restrict__ coords,
        const float* __restrict__ We1, const float* __restrict__ be1,
        const float* __restrict__ We2, const float* __restrict__ be2,
        const float* __restrict__ Wue, const float* __restrict__ bue,
        const int* __restrict__ ei, float* __restrict__ out_edge) {
    extern __shared__ float sm[];
    float* Bs      = sm;                 // 8192  (We1 -> We2 halves -> Wue)
    float* As      = Bs + 8192;          // 128*132 = 16896 (tmp then er)
    float* xs      = As + 16896;         // 128*20 = 2560
    float* score_s = xs + 2560;          // 512
    float* be1s    = score_s + 512;      // 128
    float* be2s    = be1s + 128;         // 128
    float* bues    = be2s + 128;         // 16
    int*   is_     = (int*)(bues + 16);  // 128
    int*   js_     = is_ + 128;          // 128

    int tid = threadIdx.x;
    int e0 = blockIdx.x * 128;
    float4* Bs4 = (float4*)Bs;
    float4* As4 = (float4*)As;
    float4* xs4 = (float4*)xs;
    float4* Ws4 = (float4*)Bs;

    if (tid < 128) { is_[tid] = ei[e0 + tid]; js_[tid] = ei[Ee + e0 + tid]; }
    for (int v = tid; v < 17*128; v += 256) Bs[v] = We1[v];
    if (tid < 128) { be1s[tid] = be1[tid]; be2s[tid] = be2[tid]; }
    if (tid < 16) bues[tid] = bue[tid];
    score_s[tid] = 0.f; score_s[tid + 256] = 0.f;
    {
        const float4* E4 = (const float4*)edge;
#pragma unroll
        for (int it = 0; it < 2; it++) {
            int v = tid + 256*it;
            int r = v >> 2, q = v & 3;
            xs4[r*5 + q] = E4[(size_t)(e0 + r)*4 + q];
        }
    }
    __syncthreads();
    if (tid < 128) {
        int i = is_[tid], j = js_[tid];
        float dx = coords[3*i]   - coords[3*j];
        float dy = coords[3*i+1] - coords[3*j+1];
        float dz = coords[3*i+2] - coords[3*j+2];
        xs[tid*20 + 16] = sqrtf(dx*dx + dy*dy + dz*dz + 1e-12f) * 0.1f;
    }
    __syncthreads();

    int rg = tid >> 4, cg = tid & 15;
    int r0 = rg * 8;

    // stage 1: tmp = leaky([edge,dist] @ We1 + be1)
    {
        ull acc1[8][4];
        float4 b0 = ((float4*)be1s)[cg*2], b1 = ((float4*)be1s)[cg*2 + 1];
        ull i0 = pk2(b0.x,b0.y), i1 = pk2(b0.z,b0.w), i2 = pk2(b1.x,b1.y), i3 = pk2(b1.z,b1.w);
#pragma unroll
        for (int rr = 0; rr < 8; rr++) { acc1[rr][0]=i0; acc1[rr][1]=i1; acc1[rr][2]=i2; acc1[rr][3]=i3; }
#pragma unroll
        for (int k = 0; k < 17; k++) {
            U2 w0, w1;
            w0.f = Bs4[k*32 + cg*2];
            w1.f = Bs4[k*32 + cg*2 + 1];
#pragma unroll
            for (int rr = 0; rr < 8; rr++) {
                float a = xs[(r0 + rr)*20 + k];
                ull pa = pk2(a, a);
                acc1[rr][0] = f2(pa, w0.u.lo, acc1[rr][0]);
                acc1[rr][1] = f2(pa, w0.u.hi, acc1[rr][1]);
                acc1[rr][2] = f2(pa, w1.u.lo, acc1[rr][2]);
                acc1[rr][3] = f2(pa, w1.u.hi, acc1[rr][3]);
            }
        }
#pragma unroll
        for (int rr = 0; rr < 8; rr++) {
            float2 f0 = up2(acc1[rr][0]), f1 = up2(acc1[rr][1]);
            float2 f2_ = up2(acc1[rr][2]), f3 = up2(acc1[rr][3]);
            float v[8] = { f0.x, f0.y, f1.x, f1.y, f2_.x, f2_.y, f3.x, f3.y };
#pragma unroll
            for (int q = 0; q < 8; q++) v[q] = v[q] > 0.f ? v[q] : 0.01f*v[q];
            As4[(r0 + rr)*33 + cg*2]     = make_float4(v[0], v[1], v[2], v[3]);
            As4[(r0 + rr)*33 + cg*2 + 1] = make_float4(v[4], v[5], v[6], v[7]);
        }
    }
    __syncthreads();

    // GEMM2: e = tmp @ We2 + be2
    ull acc[8][4];
    {
        float4 b0 = ((float4*)be2s)[cg*2], b1 = ((float4*)be2s)[cg*2 + 1];
        ull i0 = pk2(b0.x,b0.y), i1 = pk2(b0.z,b0.w), i2 = pk2(b1.x,b1.y), i3 = pk2(b1.z,b1.w);
#pragma unroll
        for (int rr = 0; rr < 8; rr++) { acc[rr][0]=i0; acc[rr][1]=i1; acc[rr][2]=i2; acc[rr][3]=i3; }
    }
    load_Bhalf(Bs4, (const float4*)We2, tid);
    __syncthreads();
    gemm_half(acc, Bs4, As4, 0, cg, r0);
    __syncthreads();
    load_Bhalf(Bs4, (const float4*)We2 + 2048, tid);
    __syncthreads();
    gemm_half(acc, Bs4, As4, 16, cg, r0);
    __syncthreads();

    // edge_result + scores (+ load Wue into freed Bs)
    {
        Ws4[tid]       = ((const float4*)Wue)[tid];
        Ws4[tid + 256] = ((const float4*)Wue)[tid + 256];
        const float inv = 0.17677669529663688f;
        const float4* S4 = (const float4*)g_src;
        const float4* D4 = (const float4*)g_dst;
        int h = cg >> 2;
#pragma unroll
        for (int rr = 0; rr < 8; rr++) {
            int r = r0 + rr;
            int i = is_[r], j = js_[r];
            float4 sA = S4[(size_t)j*32 + cg*2], sB = S4[(size_t)j*32 + cg*2 + 1];
            float4 dA = D4[(size_t)i*32 + cg*2], dB = D4[(size_t)i*32 + cg*2 + 1];
            float2 f0 = up2(acc[rr][0]), f1 = up2(acc[rr][1]);
            float2 f2_ = up2(acc[rr][2]), f3 = up2(acc[rr][3]);
            float e_[8];
            e_[0] = dA.x*sA.x*f0.x*inv;  e_[1] = dA.y*sA.y*f0.y*inv;
            e_[2] = dA.z*sA.z*f1.x*inv;  e_[3] = dA.w*sA.w*f1.y*inv;
            e_[4] = dB.x*sB.x*f2_.x*inv; e_[5] = dB.y*sB.y*f2_.y*inv;
            e_[6] = dB.z*sB.z*f3.x*inv;  e_[7] = dB.w*sB.w*f3.y*inv;
            float sp = fabsf(e_[0]) + fabsf(e_[1]) + fabsf(e_[2]) + fabsf(e_[3])
                     + fabsf(e_[4]) + fabsf(e_[5]) + fabsf(e_[6]) + fabsf(e_[7]);
            sp += __shfl_xor_sync(0xffffffffu, sp, 1);
            sp += __shfl_xor_sync(0xffffffffu, sp, 2);
            if ((cg & 3) == 0) atomicAdd(&score_s[r*4 + h], sp);
            As4[r*33 + cg*2]     = make_float4(e_[0], e_[1], e_[2], e_[3]);
            As4[r*33 + cg*2 + 1] = make_float4(e_[4], e_[5], e_[6], e_[7]);
        }
    }
    __syncthreads();

#pragma unroll
    for (int t = 0; t < 2; t++) {
        int v = tid + 256*t;
        int r = v >> 2, h = v & 3;
        float s = score_s[v];
        g_scores[(size_t)(e0 + r)*4 + h] = s;
        atomicMax((int*)&g_smax[is_[r]*4 + h], __float_as_int(s));
    }

    // edge_new = er @ Wue + bue (float4 As reads)
    {
        int r = tid >> 1, cp = tid & 1;
        ull acc2[4];
        float4 bb0 = ((float4*)bues)[cp*2], bb1 = ((float4*)bues)[cp*2 + 1];
        acc2[0] = pk2(bb0.x, bb0.y); acc2[1] = pk2(bb0.z, bb0.w);
        acc2[2] = pk2(bb1.x, bb1.y); acc2[3] = pk2(bb1.z, bb1.w);
        for (int k4 = 0; k4 < 32; k4++) {
            float4 a4 = As4[r*33 + k4];
#pragma unroll
            for (int kk = 0; kk < 4; kk++) {
                float a = ((float*)&a4)[kk];
                ull pa = pk2(a, a);
                int k = k4*4 + kk;
                U2 w0, w1;
                w0.f = Ws4[k*4 + cp*2];
                w1.f = Ws4[k*4 + cp*2 + 1];
                acc2[0] = f2(pa, w0.u.lo, acc2[0]);
                acc2[1] = f2(pa, w0.u.hi, acc2[1]);
                acc2[2] = f2(pa, w1.u.lo, acc2[2]);
                acc2[3] = f2(pa, w1.u.hi, acc2[3]);
            }
        }
        float2 r0_ = up2(acc2[0]), r1_ = up2(acc2[1]), r2_ = up2(acc2[2]), r3_ = up2(acc2[3]);
        ((float4*)out_edge)[(size_t)(e0 + r)*4 + cp*2]     = make_float4(r0_.x, r0_.y, r1_.x, r1_.y);
        ((float4*)out_edge)[(size_t)(e0 + r)*4 + cp*2 + 1] = make_float4(r2_.x, r2_.y, r3_.x, r3_.y);
    }
}

// ============ pass 2: exp weights, den, weighted value aggregation ============
__global__ void edge_attn(const int* __restrict__ ei) {
    int w = threadIdx.x >> 5, lane = threadIdx.x & 31;
    int e = blockIdx.x * 8 + w;
    int i = ei[e], j = ei[Ee + e];
    float ex = 0.f;
    if (lane < 4) {
        float s = g_scores[(size_t)e*4 + lane];
        float m = g_smax[i*4 + lane];
        ex = expf(s - m);
        atomicAdd(&g_den[i*4 + lane], ex);
    }
    float exh = __shfl_sync(0xffffffffu, ex, lane >> 3);
    float4 v4 = ((const float4*)g_val)[(size_t)j*32 + lane];
    float* base = &g_numer[(size_t)i*128 + lane*4];
    asm volatile("red.global.add.v4.f32 [%0], {%1,%2,%3,%4};"
                 :: "l"(base), "f"(exh*v4.x), "f"(exh*v4.y), "f"(exh*v4.z), "f"(exh*v4.w)
                 : "memory");
}

// ---------------- GraphNorm apply (output pass), float4-vectorized ----------------
__global__ void k_norm4(const float* __restrict__ w_, const float* __restrict__ b_,
                        const float* __restrict__ a_, const int* __restrict__ batch,
                        const float* __restrict__ X, float* __restrict__ Y, int statoff) {
    int idx = blockIdx.x*256 + threadIdx.x;
    if (idx >= Nn*32) return;
    int n = idx >> 5, q = idx & 31;
    int b = batch[n];
    float rc = 1.f / fmaxf(g_stats[4*Gg*Hh + b], 1.f);
    float4 s1 = *(const float4*)&g_stats[statoff + b*Hh + q*4];
    float4 s2 = *(const float4*)&g_stats[statoff + Gg*Hh + b*Hh + q*4];
    float4 x = ((const float4*)X)[(size_t)n*32 + q];
    float4 y = gnorm4(x, s1, s2, rc,
                      ((const float4*)a_)[q], ((const float4*)w_)[q], ((const float4*)b_)[q]);
    ((float4*)Y)[(size_t)n*32 + q] = y;
}

// ---------------- launch ----------------
extern "C" void kernel_launch(void* const* d_in, const int* in_sizes, int n_in,
                              void* d_out, int out_size) {
    const float* node = (const float*)d_in[0];
    const float* edge = (const float*)d_in[1];
    const float* coords = (const float*)d_in[2];
    const float* Ws = (const float*)d_in[3];  const float* bs = (const float*)d_in[4];
    const float* Wd = (const float*)d_in[5];  const float* bd = (const float*)d_in[6];
    const float* Wv = (const float*)d_in[7];  const float* bv = (const float*)d_in[8];
    const float* We1 = (const float*)d_in[9]; const float* be1 = (const float*)d_in[10];
    const float* We2 = (const float*)d_in[11];const float* be2 = (const float*)d_in[12];
    const float* Wun = (const float*)d_in[13];const float* bun = (const float*)d_in[14];
    const float* Wue = (const float*)d_in[15];const float* bue = (const float*)d_in[16];
    const float* Wg  = (const float*)d_in[17];const float* bg  = (const float*)d_in[18];
    const float* Wf1 = (const float*)d_in[19];const float* bf1 = (const float*)d_in[20];
    const float* Wf2 = (const float*)d_in[21];const float* bf2 = (const float*)d_in[22];
    const float* gn1w = (const float*)d_in[23];
    const float* gn1b = (const float*)d_in[24];
    const float* gn1a = (const float*)d_in[25];
    const float* gn2w = (const float*)d_in[26];
    const float* gn2b = (const float*)d_in[27];
    const float* gn2a = (const float*)d_in[28];
    const int* ei = (const int*)d_in[29];
    const int* batch = (const int*)d_in[30];

    float* out = (float*)d_out;
    float* out_n2 = out;
    float* out_edge = out + (size_t)Nn*Hh;
    float* out_coords = out + (size_t)Nn*Hh + (size_t)Ee*16;

    size_t g64_smem = (8192 + 64*132) * sizeof(float);                    // 66560
    size_t ef_smem  = (8192 + 16896 + 2560 + 512 + 128 + 128 + 16) * sizeof(float)
                    + 256 * sizeof(int);                                   // 114752
    cudaFuncSetAttribute(gemm_proj,    cudaFuncAttributeMaxDynamicSharedMemorySize, (int)g64_smem);
    cudaFuncSetAttribute(gemm_nngate,  cudaFuncAttributeMaxDynamicSharedMemorySize, (int)g64_smem);
    cudaFuncSetAttribute(gemm_fix_h2,  cudaFuncAttributeMaxDynamicSharedMemorySize, (int)g64_smem);
    cudaFuncSetAttribute(edge_fused,   cudaFuncAttributeMaxDynamicSharedMemorySize, (int)ef_smem);

    float *p_src,*p_dst,*p_val,*p_h2;
    void* p;
    cudaGetSymbolAddress(&p, g_src); p_src = (float*)p;
    cudaGetSymbolAddress(&p, g_dst); p_dst = (float*)p;
    cudaGetSymbolAddress(&p, g_val); p_val = (float*)p;
    cudaGetSymbolAddress(&p, g_h2); p_h2 = (float*)p;

    cudaGetSymbolAddress(&p, g_smax);  cudaMemsetAsync(p, 0, sizeof(float)*Nn*NHh, 0);
    cudaGetSymbolAddress(&p, g_den);   cudaMemsetAsync(p, 0, sizeof(float)*Nn*NHh, 0);
    cudaGetSymbolAddress(&p, g_numer); cudaMemsetAsync(p, 0, sizeof(float)*Nn*Hh, 0);
    cudaGetSymbolAddress(&p, g_stats); cudaMemsetAsync(p, 0, sizeof(float)*(4*Gg*Hh + Gg), 0);

    int vecGrid  = (Nn*32 + 255) / 256;     // 3750
    int edgeWGrid = Ee / 8;                 // 60000
    int edgeFGrid = Ee / 128;               // 3750

    // node projections: 3*NT64 independent (tile64, weight) tasks
    gemm_proj<<<3*NT64, 256, g64_smem>>>(node, Ws, bs, p_src, Wd, bd, p_dst, Wv, bv, p_val);

    // fused edge pipeline
    edge_fused<<<edgeFGrid, 256, ef_smem>>>(edge, coords, We1, be1, We2, be2,
                                            Wue, bue, ei, out_edge);

    // softmax + aggregation
    edge_attn<<<edgeWGrid, 256>>>(ei);

    // merged: nodenew GEMM + gate + h1 + stats1 (64-row tiles, 3 CTAs/SM)
    gemm_nngate<<<NT64, 256, g64_smem>>>(node, Wun, bun, Wg, bg, batch);

    // fix_node with inline norm1 + h2 + stats2 (64-row tiles, 3 CTAs/SM)
    gemm_fix_h2<<<NT64, 256, g64_smem>>>(Wf1, bf1, Wf2, bf2, gn1w, gn1b, gn1a, batch);

    // norm2 -> output
    k_norm4<<<vecGrid, 256>>>(gn2w, gn2b, gn2a, batch, p_h2, out_n2, 2*Gg*Hh);

    // coords pass-through
    cudaMemcpyAsync(out_coords, coords, sizeof(float)*Nn*3, cudaMemcpyDeviceToDevice, 0);

    (void)in_sizes; (void)n_in; (void)out_size;
}

// round 16
// speedup vs baseline: 1.0107x; 1.0107x over previous
#include <cuda_runtime.h>
#include <math.h>

#define Nn 30000
#define Ee 480000
#define Hh 128
#define NHh 4
#define Gg 64
#define EPSf 1e-5f
#define NTILES 235

typedef unsigned long long ull;
union U2 { float4 f; struct { ull lo, hi; } u; };

__device__ __forceinline__ ull pk2(float x, float y) {
    ull r; asm("mov.b64 %0,{%1,%2};" : "=l"(r) : "f"(x), "f"(y)); return r;
}
__device__ __forceinline__ ull f2(ull a, ull b, ull c) {
    ull d; asm("fma.rn.f32x2 %0,%1,%2,%3;" : "=l"(d) : "l"(a), "l"(b), "l"(c)); return d;
}
__device__ __forceinline__ float2 up2(ull v) {
    float2 f; asm("mov.b64 {%0,%1},%2;" : "=f"(f.x), "=f"(f.y) : "l"(v)); return f;
}
__device__ __forceinline__ void red4(float* p, float4 v) {
    asm volatile("red.global.add.v4.f32 [%0],{%1,%2,%3,%4};"
                 :: "l"(p), "f"(v.x), "f"(v.y), "f"(v.z), "f"(v.w) : "memory");
}
__device__ __forceinline__ void red1(float* p, float v) {
    asm volatile("red.global.add.f32 [%0],%1;" :: "l"(p), "f"(v) : "memory");
}

// ---------------- scratch (device globals) ----------------
__device__ float g_src[Nn*Hh];
__device__ float g_dst[Nn*Hh];
__device__ float g_val[Nn*Hh];
__device__ float g_gpart[Nn*Hh];     // node@Wg2 + bg (precomputed)
__device__ float g_scores[(size_t)Ee*NHh];
__device__ float g_smax[Nn*NHh];
__device__ float g_den[Nn*NHh];
__device__ float g_numer[Nn*Hh];
__device__ float g_nodenew[Nn*Hh];
__device__ float g_gate[Nn*Hh];
__device__ float g_h1[Nn*Hh];
__device__ float g_h2[Nn*Hh];
// [0,GH) sum1 | [GH,2GH) sq1 | [2GH,3GH) sum2 | [3GH,4GH) sq2 | [4GH,4GH+G) cnt
__device__ float g_stats[4*Gg*Hh + Gg];

// load half of a 128x128 B (64 K-rows) de-interleaved into Bs (2048 float4)
__device__ __forceinline__ void load_Bhalf(float4* Bs4, const float4* B4half, int tid) {
#pragma unroll
    for (int it = 0; it < 8; it++) {
        int v = tid + 256*it;
        int c4 = v & 31;
        Bs4[(v & ~31) | (((c4 & 1) << 4) | (c4 >> 1))] = B4half[v];
    }
}

// combined-weight B-half loader: z = Wa + sgn*Wb
__device__ __forceinline__ void load_Bhalf_comb(float4* Bs4, const float4* Wa,
                                                const float4* Wb, float sgn, int tid) {
#pragma unroll
    for (int it = 0; it < 8; it++) {
        int v = tid + 256*it;
        int c4 = v & 31;
        float4 x = Wa[v], y = Wb[v];
        float4 z = make_float4(x.x + sgn*y.x, x.y + sgn*y.y, x.z + sgn*y.z, x.w + sgn*y.w);
        Bs4[(v & ~31) | (((c4 & 1) << 4) | (c4 >> 1))] = z;
    }
}

// 16 k4-steps of the 8x8 f32x2 GEMM inner loop
__device__ __forceinline__ void gemm_half(ull acc[8][4], const float4* Bs4, const float4* As4,
                                          int k4_0, int cg, int r0) {
    for (int k4 = k4_0; k4 < k4_0 + 16; k4++) {
        float4 a4[8];
#pragma unroll
        for (int rr = 0; rr < 8; rr++) a4[rr] = As4[(r0 + rr)*33 + k4];
#pragma unroll
        for (int kk = 0; kk < 4; kk++) {
            U2 w0, w1;
            w0.f = Bs4[((k4 - k4_0)*4 + kk)*32 + cg];
            w1.f = Bs4[((k4 - k4_0)*4 + kk)*32 + 16 + cg];
#pragma unroll
            for (int rr = 0; rr < 8; rr++) {
                float a = ((float*)&a4[rr])[kk];
                ull pa = pk2(a, a);
                acc[rr][0] = f2(pa, w0.u.lo, acc[rr][0]);
                acc[rr][1] = f2(pa, w0.u.hi, acc[rr][1]);
                acc[rr][2] = f2(pa, w1.u.lo, acc[rr][2]);
                acc[rr][3] = f2(pa, w1.u.hi, acc[rr][3]);
            }
        }
    }
}

__device__ __forceinline__ void load_Atile(float4* As4, const float4* A4, int row0, int tid) {
#pragma unroll
    for (int it = 0; it < 16; it++) {
        int v = tid + 256*it;
        int r = v >> 5, q = v & 31;
        As4[r*33 + q] = (row0 + r < Nn) ? A4[(size_t)(row0 + r)*32 + q]
                                        : make_float4(0.f,0.f,0.f,0.f);
    }
}

// GraphNorm on a float4 (must match everywhere for consistency)
__device__ __forceinline__ float4 gnorm4(float4 x, float4 s1, float4 s2, float rc,
                                         float4 a, float4 w, float4 bb) {
    float4 y;
    {
        float mean = s1.x*rc, m2 = s2.x*rc;
        float var = m2 + mean*mean*(a.x*a.x - 2.f*a.x);
        y.x = w.x * (x.x - a.x*mean) * rsqrtf(var + EPSf) + bb.x;
    }
    {
        float mean = s1.y*rc, m2 = s2.y*rc;
        float var = m2 + mean*mean*(a.y*a.y - 2.f*a.y);
        y.y = w.y * (x.y - a.y*mean) * rsqrtf(var + EPSf) + bb.y;
    }
    {
        float mean = s1.z*rc, m2 = s2.z*rc;
        float var = m2 + mean*mean*(a.z*a.z - 2.f*a.z);
        y.z = w.z * (x.z - a.z*mean) * rsqrtf(var + EPSf) + bb.z;
    }
    {
        float mean = s1.w*rc, m2 = s2.w*rc;
        float var = m2 + mean*mean*(a.w*a.w - 2.f*a.w);
        y.w = w.w * (x.w - a.w*mean) * rsqrtf(var + EPSf) + bb.w;
    }
    return y;
}

// ============ projection: task = (tile, weight); grid = 4*NTILES ============
// w=0..2: src/dst/val. w=3: gpart = node@(Wg[H:2H]-Wg[2H:3H]) + bg.
__global__ __launch_bounds__(256, 2) void gemm_proj(
        const float* __restrict__ A,
        const float* __restrict__ B0, const float* __restrict__ b0, float* __restrict__ C0,
        const float* __restrict__ B1, const float* __restrict__ b1, float* __restrict__ C1,
        const float* __restrict__ B2, const float* __restrict__ b2, float* __restrict__ C2,
        const float* __restrict__ Wg, const float* __restrict__ bg) {
    extern __shared__ float sm[];
    float4* Bs4 = (float4*)sm;
    float4* As4 = (float4*)(sm + 8192);
    int tid = threadIdx.x;
    int w = blockIdx.x / NTILES;
    int row0 = (blockIdx.x % NTILES) * 128;
    const float4* Wg4 = (const float4*)Wg;
    const float* bias = (w == 0) ? b0 : (w == 1) ? b1 : (w == 2) ? b2 : bg;
    float* C;
    { void* p; asm("mov.u64 %0, g_gpart;" : "=l"(p)); // avoid host symbol lookup: use address directly
      C = (w == 0) ? C0 : (w == 1) ? C1 : (w == 2) ? C2 : (float*)p; }

    load_Atile(As4, (const float4*)A, row0, tid);
    if (w < 3) {
        const float4* B4 = (const float4*)((w == 0) ? B0 : (w == 1) ? B1 : B2);
        load_Bhalf(Bs4, B4, tid);
    } else {
        load_Bhalf_comb(Bs4, Wg4 + 4096, Wg4 + 8192, -1.f, tid);
    }
    __syncthreads();
    int rg = tid >> 4, cg = tid & 15;
    int r0 = rg * 8;
    ull acc[8][4];
#pragma unroll
    for (int rr = 0; rr < 8; rr++) { acc[rr][0]=0; acc[rr][1]=0; acc[rr][2]=0; acc[rr][3]=0; }
    gemm_half(acc, Bs4, As4, 0, cg, r0);
    __syncthreads();
    if (w < 3) {
        const float4* B4 = (const float4*)((w == 0) ? B0 : (w == 1) ? B1 : B2);
        load_Bhalf(Bs4, B4 + 2048, tid);
    } else {
        load_Bhalf_comb(Bs4, Wg4 + 4096 + 2048, Wg4 + 8192 + 2048, -1.f, tid);
    }
    __syncthreads();
    gemm_half(acc, Bs4, As4, 16, cg, r0);
    float4 bi0 = ((const float4*)bias)[cg*2];
    float4 bi1 = ((const float4*)bias)[cg*2 + 1];
#pragma unroll
    for (int rr = 0; rr < 8; rr++) {
        int r = row0 + r0 + rr;
        if (r < Nn) {
            float2 f0 = up2(acc[rr][0]), f1 = up2(acc[rr][1]);
            float2 f2_ = up2(acc[rr][2]), f3 = up2(acc[rr][3]);
            ((float4*)C)[(size_t)r*32 + cg*2]     = make_float4(f0.x+bi0.x, f0.y+bi0.y, f1.x+bi0.z, f1.y+bi0.w);
            ((float4*)C)[(size_t)r*32 + cg*2 + 1] = make_float4(f2_.x+bi1.x, f2_.y+bi1.y, f3.x+bi1.z, f3.y+bi1.w);
        }
    }
}

// ============ merged: nodenew GEMM + gate (1 GEMM + gpart) + sigmoid + h1 + stats1 ============
__global__ __launch_bounds__(256, 2) void gemm_nngate(
        const float* __restrict__ node,
        const float* __restrict__ Wun, const float* __restrict__ bun,
        const float* __restrict__ Wg,
        const int* __restrict__ batch) {
    extern __shared__ float sm[];
    float4* Bs4 = (float4*)sm;
    float4* As4 = (float4*)(sm + 8192);
    int tid = threadIdx.x;
    int row0 = blockIdx.x * 128;
    int rg = tid >> 4, cg = tid & 15;
    int r0 = rg * 8;
    const float4* Wg4 = (const float4*)Wg;

    // ---- PHASE A: nodenew = (numer/den)@Wun + bun ----
#pragma unroll
    for (int it = 0; it < 16; it++) {
        int v = tid + 256*it;
        int r = v >> 5, q = v & 31;
        float4 x = make_float4(0.f,0.f,0.f,0.f);
        int row = row0 + r;
        if (row < Nn) {
            x = ((const float4*)g_numer)[(size_t)row*32 + q];
            float dv = g_den[row*4 + (q >> 3)];
            float inv = (dv > 0.f) ? __fdividef(1.f, dv) : 0.f;
            x.x *= inv; x.y *= inv; x.z *= inv; x.w *= inv;
        }
        As4[r*33 + q] = x;
    }
    ull acc[8][4];
#pragma unroll
    for (int rr = 0; rr < 8; rr++) { acc[rr][0]=0; acc[rr][1]=0; acc[rr][2]=0; acc[rr][3]=0; }
    load_Bhalf(Bs4, (const float4*)Wun, tid);
    __syncthreads();
    gemm_half(acc, Bs4, As4, 0, cg, r0);
    __syncthreads();
    load_Bhalf(Bs4, (const float4*)Wun + 2048, tid);
    __syncthreads();
    gemm_half(acc, Bs4, As4, 16, cg, r0);
    __syncthreads();   // all reads of numer tile done
    // write nodenew (with bias) into As (A-tile for gate GEMM) and g_nodenew
    {
        float4 bi0 = ((const float4*)bun)[cg*2];
        float4 bi1 = ((const float4*)bun)[cg*2 + 1];
#pragma unroll
        for (int rr = 0; rr < 8; rr++) {
            int r = row0 + r0 + rr;
            float2 f0 = up2(acc[rr][0]), f1 = up2(acc[rr][1]);
            float2 f2_ = up2(acc[rr][2]), f3 = up2(acc[rr][3]);
            float4 v0 = make_float4(f0.x+bi0.x, f0.y+bi0.y, f1.x+bi0.z, f1.y+bi0.w);
            float4 v1 = make_float4(f2_.x+bi1.x, f2_.y+bi1.y, f3.x+bi1.z, f3.y+bi1.w);
            As4[(r0 + rr)*33 + cg*2]     = v0;
            As4[(r0 + rr)*33 + cg*2 + 1] = v1;
            if (r < Nn) {
                ((float4*)g_nodenew)[(size_t)r*32 + cg*2]     = v0;
                ((float4*)g_nodenew)[(size_t)r*32 + cg*2 + 1] = v1;
            }
        }
    }
    __syncthreads();

    // ---- PHASE B: accG = nodenew(As) @ (Wg[0:H] + Wg[2H:3H]) ----
#pragma unroll
    for (int rr = 0; rr < 8; rr++) { acc[rr][0]=0; acc[rr][1]=0; acc[rr][2]=0; acc[rr][3]=0; }
    load_Bhalf_comb(Bs4, Wg4, Wg4 + 8192, 1.f, tid);
    __syncthreads();
    gemm_half(acc, Bs4, As4, 0, cg, r0);
    __syncthreads();
    load_Bhalf_comb(Bs4, Wg4 + 2048, Wg4 + 8192 + 2048, 1.f, tid);
    __syncthreads();
    gemm_half(acc, Bs4, As4, 16, cg, r0);

    // ---- EPILOGUE: gate = sigmoid(accG + gpart); h1 = g*nodenew + node; stats ----
    // nodenew read from As (still resident); node and gpart from global (L2).
#pragma unroll
    for (int rr = 0; rr < 8; rr++) {
        int r = row0 + r0 + rr;
        if (r < Nn) {
            float4 gp0 = ((const float4*)g_gpart)[(size_t)r*32 + cg*2];
            float4 gp1 = ((const float4*)g_gpart)[(size_t)r*32 + cg*2 + 1];
            float2 f0 = up2(acc[rr][0]), f1 = up2(acc[rr][1]);
            float2 f2_ = up2(acc[rr][2]), f3 = up2(acc[rr][3]);
            float4 v0 = make_float4(f0.x+gp0.x, f0.y+gp0.y, f1.x+gp0.z, f1.y+gp0.w);
            float4 v1 = make_float4(f2_.x+gp1.x, f2_.y+gp1.y, f3.x+gp1.z, f3.y+gp1.w);
            v0.x = 1.f/(1.f+expf(-v0.x)); v0.y = 1.f/(1.f+expf(-v0.y));
            v0.z = 1.f/(1.f+expf(-v0.z)); v0.w = 1.f/(1.f+expf(-v0.w));
            v1.x = 1.f/(1.f+expf(-v1.x)); v1.y = 1.f/(1.f+expf(-v1.y));
            v1.z = 1.f/(1.f+expf(-v1.z)); v1.w = 1.f/(1.f+expf(-v1.w));
            ((float4*)g_gate)[(size_t)r*32 + cg*2]     = v0;
            ((float4*)g_gate)[(size_t)r*32 + cg*2 + 1] = v1;
            float4 nn0 = As4[(r0 + rr)*33 + cg*2];        // nodenew tile resident
            float4 nn1 = As4[(r0 + rr)*33 + cg*2 + 1];
            float4 nd0 = ((const float4*)node)[(size_t)r*32 + cg*2];
            float4 nd1 = ((const float4*)node)[(size_t)r*32 + cg*2 + 1];
            float4 h0 = make_float4(v0.x*nn0.x+nd0.x, v0.y*nn0.y+nd0.y,
                                    v0.z*nn0.z+nd0.z, v0.w*nn0.w+nd0.w);
            float4 h1v = make_float4(v1.x*nn1.x+nd1.x, v1.y*nn1.y+nd1.y,
                                     v1.z*nn1.z+nd1.z, v1.w*nn1.w+nd1.w);
            ((float4*)g_h1)[(size_t)r*32 + cg*2]     = h0;
            ((float4*)g_h1)[(size_t)r*32 + cg*2 + 1] = h1v;
            int b = batch[r];
            red4(&g_stats[b*Hh + cg*8],     h0);
            red4(&g_stats[b*Hh + cg*8 + 4], h1v);
            red4(&g_stats[Gg*Hh + b*Hh + cg*8],
                 make_float4(h0.x*h0.x, h0.y*h0.y, h0.z*h0.z, h0.w*h0.w));
            red4(&g_stats[Gg*Hh + b*Hh + cg*8 + 4],
                 make_float4(h1v.x*h1v.x, h1v.y*h1v.y, h1v.z*h1v.z, h1v.w*h1v.w));
            if (cg == 0) red1(&g_stats[4*Gg*Hh + b], 1.f);
        }
    }
}

// ============ fused fix_node with inline norm1 (R14 128-row version) ============
__global__ __launch_bounds__(256, 2) void gemm_fix_h2(
        const float* __restrict__ Wf1, const float* __restrict__ bf1,
        const float* __restrict__ Wf2, const float* __restrict__ bf2,
        const float* __restrict__ gn1w, const float* __restrict__ gn1b,
        const float* __restrict__ gn1a, const int* __restrict__ batch) {
    extern __shared__ float sm[];
    float4* Bs4 = (float4*)sm;
    float4* As4 = (float4*)(sm + 8192);
    int tid = threadIdx.x;
    int row0 = blockIdx.x * 128;
    int rg = tid >> 4, cg = tid & 15;
    int r0 = rg * 8;

#pragma unroll
    for (int it = 0; it < 16; it++) {
        int v = tid + 256*it;
        int r = v >> 5, q = v & 31;
        int row = row0 + r;
        float4 x = make_float4(0.f,0.f,0.f,0.f);
        if (row < Nn) {
            x = ((const float4*)g_h1)[(size_t)row*32 + q];
            int b = batch[row];
            float rc = 1.f / fmaxf(g_stats[4*Gg*Hh + b], 1.f);
            float4 s1 = *(const float4*)&g_stats[b*Hh + q*4];
            float4 s2 = *(const float4*)&g_stats[Gg*Hh + b*Hh + q*4];
            x = gnorm4(x, s1, s2, rc,
                       ((const float4*)gn1a)[q], ((const float4*)gn1w)[q],
                       ((const float4*)gn1b)[q]);
        }
        As4[r*33 + q] = x;
    }
    ull acc[8][4];
#pragma unroll
    for (int rr = 0; rr < 8; rr++) { acc[rr][0]=0; acc[rr][1]=0; acc[rr][2]=0; acc[rr][3]=0; }
    load_Bhalf(Bs4, (const float4*)Wf1, tid);
    __syncthreads();
    gemm_half(acc, Bs4, As4, 0, cg, r0);
    __syncthreads();
    load_Bhalf(Bs4, (const float4*)Wf1 + 2048, tid);
    __syncthreads();
    gemm_half(acc, Bs4, As4, 16, cg, r0);
    __syncthreads();
    {
        float4 bi0 = ((const float4*)bf1)[cg*2];
        float4 bi1 = ((const float4*)bf1)[cg*2 + 1];
#pragma unroll
        for (int rr = 0; rr < 8; rr++) {
            float2 f0 = up2(acc[rr][0]), f1 = up2(acc[rr][1]);
            float2 f2_ = up2(acc[rr][2]), f3 = up2(acc[rr][3]);
            float v[8] = { f0.x+bi0.x, f0.y+bi0.y, f1.x+bi0.z, f1.y+bi0.w,
                           f2_.x+bi1.x, f2_.y+bi1.y, f3.x+bi1.z, f3.y+bi1.w };
#pragma unroll
            for (int q = 0; q < 8; q++) v[q] = v[q] > 0.f ? v[q] : 0.01f*v[q];
            As4[(r0 + rr)*33 + cg*2]     = make_float4(v[0], v[1], v[2], v[3]);
            As4[(r0 + rr)*33 + cg*2 + 1] = make_float4(v[4], v[5], v[6], v[7]);
        }
    }
    __syncthreads();
#pragma unroll
    for (int rr = 0; rr < 8; rr++) { acc[rr][0]=0; acc[rr][1]=0; acc[rr][2]=0; acc[rr][3]=0; }
    load_Bhalf(Bs4, (const float4*)Wf2, tid);
    __syncthreads();
    gemm_half(acc, Bs4, As4, 0, cg, r0);
    __syncthreads();
    load_Bhalf(Bs4, (const float4*)Wf2 + 2048, tid);
    __syncthreads();
    gemm_half(acc, Bs4, As4, 16, cg, r0);

    float4 bi0 = ((const float4*)bf2)[cg*2];
    float4 bi1 = ((const float4*)bf2)[cg*2 + 1];
#pragma unroll
    for (int rr = 0; rr < 8; rr++) {
        int r = row0 + r0 + rr;
        if (r < Nn) {
            float2 f0 = up2(acc[rr][0]), f1 = up2(acc[rr][1]);
            float2 f2_ = up2(acc[rr][2]), f3 = up2(acc[rr][3]);
            float4 x0 = make_float4(f0.x+bi0.x, f0.y+bi0.y, f1.x+bi0.z, f1.y+bi0.w);
            float4 x1 = make_float4(f2_.x+bi1.x, f2_.y+bi1.y, f3.x+bi1.z, f3.y+bi1.w);
            int b = batch[r];
            float rc = 1.f / fmaxf(g_stats[4*Gg*Hh + b], 1.f);
            int q0 = cg*2, q1 = cg*2 + 1;
            float4 h1a = ((const float4*)g_h1)[(size_t)r*32 + q0];
            float4 h1b = ((const float4*)g_h1)[(size_t)r*32 + q1];
            float4 n10 = gnorm4(h1a, *(const float4*)&g_stats[b*Hh + q0*4],
                                *(const float4*)&g_stats[Gg*Hh + b*Hh + q0*4], rc,
                                ((const float4*)gn1a)[q0], ((const float4*)gn1w)[q0],
                                ((const float4*)gn1b)[q0]);
            float4 n11 = gnorm4(h1b, *(const float4*)&g_stats[b*Hh + q1*4],
                                *(const float4*)&g_stats[Gg*Hh + b*Hh + q1*4], rc,
                                ((const float4*)gn1a)[q1], ((const float4*)gn1w)[q1],
                                ((const float4*)gn1b)[q1]);
            float4 gg0 = ((const float4*)g_gate)[(size_t)r*32 + q0];
            float4 gg1 = ((const float4*)g_gate)[(size_t)r*32 + q1];
            float4 h0 = make_float4(gg0.x*x0.x+n10.x, gg0.y*x0.y+n10.y,
                                    gg0.z*x0.z+n10.z, gg0.w*x0.w+n10.w);
            float4 h1v = make_float4(gg1.x*x1.x+n11.x, gg1.y*x1.y+n11.y,
                                     gg1.z*x1.z+n11.z, gg1.w*x1.w+n11.w);
            ((float4*)g_h2)[(size_t)r*32 + q0] = h0;
            ((float4*)g_h2)[(size_t)r*32 + q1] = h1v;
            red4(&g_stats[2*Gg*Hh + b*Hh + cg*8],     h0);
            red4(&g_stats[2*Gg*Hh + b*Hh + cg*8 + 4], h1v);
            red4(&g_stats[3*Gg*Hh + b*Hh + cg*8],
                 make_float4(h0.x*h0.x, h0.y*h0.y, h0.z*h0.z, h0.w*h0.w));
            red4(&g_stats[3*Gg*Hh + b*Hh + cg*8 + 4],
                 make_float4(h1v.x*h1v.x, h1v.y*h1v.y, h1v.z*h1v.z, h1v.w*h1v.w));
        }
    }
}

// ============ fused edge kernel (UNCHANGED) ============
__global__ __launch_bounds__(256, 2) void edge_fused(
        const float* __restrict__ edge, const float* __restrict__ coords,
        const float* __restrict__ We1, const float* __restrict__ be1,
        const float* __restrict__ We2, const float* __restrict__ be2,
        const float* __restrict__ Wue, const float* __restrict__ bue,
        const int* __restrict__ ei, float* __restrict__ out_edge) {
    extern __shared__ float sm[];
    float* Bs      = sm;                 // 8192  (We1 -> We2 halves -> Wue)
    float* As      = Bs + 8192;          // 128*132 = 16896 (tmp then er)
    float* xs      = As + 16896;         // 128*20 = 2560
    float* score_s = xs + 2560;          // 512
    float* be1s    = score_s + 512;      // 128
    float* be2s    = be1s + 128;         // 128
    float* bues    = be2s + 128;         // 16
    int*   is_     = (int*)(bues + 16);  // 128
    int*   js_     = is_ + 128;          // 128

    int tid = threadIdx.x;
    int e0 = blockIdx.x * 128;
    float4* Bs4 = (float4*)Bs;
    float4* As4 = (float4*)As;
    float4* xs4 = (float4*)xs;
    float4* Ws4 = (float4*)Bs;

    if (tid < 128) { is_[tid] = ei[e0 + tid]; js_[tid] = ei[Ee + e0 + tid]; }
    for (int v = tid; v < 17*128; v += 256) Bs[v] = We1[v];
    if (tid < 128) { be1s[tid] = be1[tid]; be2s[tid] = be2[tid]; }
    if (tid < 16) bues[tid] = bue[tid];
    score_s[tid] = 0.f; score_s[tid + 256] = 0.f;
    {
        const float4* E4 = (const float4*)edge;
#pragma unroll
        for (int it = 0; it < 2; it++) {
            int v = tid + 256*it;
            int r = v >> 2, q = v & 3;
            xs4[r*5 + q] = E4[(size_t)(e0 + r)*4 + q];
        }
    }
    __syncthreads();
    if (tid < 128) {
        int i = is_[tid], j = js_[tid];
        float dx = coords[3*i]   - coords[3*j];
        float dy = coords[3*i+1] - coords[3*j+1];
        float dz = coords[3*i+2] - coords[3*j+2];
        xs[tid*20 + 16] = sqrtf(dx*dx + dy*dy + dz*dz + 1e-12f) * 0.1f;
    }
    __syncthreads();

    int rg = tid >> 4, cg = tid & 15;
    int r0 = rg * 8;

    // stage 1: tmp = leaky([edge,dist] @ We1 + be1)
    {
        ull acc1[8][4];
        float4 b0 = ((float4*)be1s)[cg*2], b1 = ((float4*)be1s)[cg*2 + 1];
        ull i0 = pk2(b0.x,b0.y), i1 = pk2(b0.z,b0.w), i2 = pk2(b1.x,b1.y), i3 = pk2(b1.z,b1.w);
#pragma unroll
        for (int rr = 0; rr < 8; rr++) { acc1[rr][0]=i0; acc1[rr][1]=i1; acc1[rr][2]=i2; acc1[rr][3]=i3; }
#pragma unroll
        for (int k = 0; k < 17; k++) {
            U2 w0, w1;
            w0.f = Bs4[k*32 + cg*2];
            w1.f = Bs4[k*32 + cg*2 + 1];
#pragma unroll
            for (int rr = 0; rr < 8; rr++) {
                float a = xs[(r0 + rr)*20 + k];
                ull pa = pk2(a, a);
                acc1[rr][0] = f2(pa, w0.u.lo, acc1[rr][0]);
                acc1[rr][1] = f2(pa, w0.u.hi, acc1[rr][1]);
                acc1[rr][2] = f2(pa, w1.u.lo, acc1[rr][2]);
                acc1[rr][3] = f2(pa, w1.u.hi, acc1[rr][3]);
            }
        }
#pragma unroll
        for (int rr = 0; rr < 8; rr++) {
            float2 f0 = up2(acc1[rr][0]), f1 = up2(acc1[rr][1]);
            float2 f2_ = up2(acc1[rr][2]), f3 = up2(acc1[rr][3]);
            float v[8] = { f0.x, f0.y, f1.x, f1.y, f2_.x, f2_.y, f3.x, f3.y };
#pragma unroll
            for (int q = 0; q < 8; q++) v[q] = v[q] > 0.f ? v[q] : 0.01f*v[q];
            As4[(r0 + rr)*33 + cg*2]     = make_float4(v[0], v[1], v[2], v[3]);
            As4[(r0 + rr)*33 + cg*2 + 1] = make_float4(v[4], v[5], v[6], v[7]);
        }
    }
    __syncthreads();

    // GEMM2: e = tmp @ We2 + be2
    ull acc[8][4];
    {
        float4 b0 = ((float4*)be2s)[cg*2], b1 = ((float4*)be2s)[cg*2 + 1];
        ull i0 = pk2(b0.x,b0.y), i1 = pk2(b0.z,b0.w), i2 = pk2(b1.x,b1.y), i3 = pk2(b1.z,b1.w);
#pragma unroll
        for (int rr = 0; rr < 8; rr++) { acc[rr][0]=i0; acc[rr][1]=i1; acc[rr][2]=i2; acc[rr][3]=i3; }
    }
    load_Bhalf(Bs4, (const float4*)We2, tid);
    __syncthreads();
    gemm_half(acc, Bs4, As4, 0, cg, r0);
    __syncthreads();
    load_Bhalf(Bs4, (const float4*)We2 + 2048, tid);
    __syncthreads();
    gemm_half(acc, Bs4, As4, 16, cg, r0);
    __syncthreads();

    // edge_result + scores (+ load Wue into freed Bs)
    {
        Ws4[tid]       = ((const float4*)Wue)[tid];
        Ws4[tid + 256] = ((const float4*)Wue)[tid + 256];
        const float inv = 0.17677669529663688f;
        const float4* S4 = (const float4*)g_src;
        const float4* D4 = (const float4*)g_dst;
        int h = cg >> 2;
#pragma unroll
        for (int rr = 0; rr < 8; rr++) {
            int r = r0 + rr;
            int i = is_[r], j = js_[r];
            float4 sA = S4[(size_t)j*32 + cg*2], sB = S4[(size_t)j*32 + cg*2 + 1];
            float4 dA = D4[(size_t)i*32 + cg*2], dB = D4[(size_t)i*32 + cg*2 + 1];
            float2 f0 = up2(acc[rr][0]), f1 = up2(acc[rr][1]);
            float2 f2_ = up2(acc[rr][2]), f3 = up2(acc[rr][3]);
            float e_[8];
            e_[0] = dA.x*sA.x*f0.x*inv;  e_[1] = dA.y*sA.y*f0.y*inv;
            e_[2] = dA.z*sA.z*f1.x*inv;  e_[3] = dA.w*sA.w*f1.y*inv;
            e_[4] = dB.x*sB.x*f2_.x*inv; e_[5] = dB.y*sB.y*f2_.y*inv;
            e_[6] = dB.z*sB.z*f3.x*inv;  e_[7] = dB.w*sB.w*f3.y*inv;
            float sp = fabsf(e_[0]) + fabsf(e_[1]) + fabsf(e_[2]) + fabsf(e_[3])
                     + fabsf(e_[4]) + fabsf(e_[5]) + fabsf(e_[6]) + fabsf(e_[7]);
            sp += __shfl_xor_sync(0xffffffffu, sp, 1);
            sp += __shfl_xor_sync(0xffffffffu, sp, 2);
            if ((cg & 3) == 0) atomicAdd(&score_s[r*4 + h], sp);
            As4[r*33 + cg*2]     = make_float4(e_[0], e_[1], e_[2], e_[3]);
            As4[r*33 + cg*2 + 1] = make_float4(e_[4], e_[5], e_[6], e_[7]);
        }
    }
    __syncthreads();

#pragma unroll
    for (int t = 0; t < 2; t++) {
        int v = tid + 256*t;
        int r = v >> 2, h = v & 3;
        float s = score_s[v];
        g_scores[(size_t)(e0 + r)*4 + h] = s;
        atomicMax((int*)&g_smax[is_[r]*4 + h], __float_as_int(s));
    }

    // edge_new = er @ Wue + bue (float4 As reads)
    {
        int r = tid >> 1, cp = tid & 1;
        ull acc2[4];
        float4 bb0 = ((float4*)bues)[cp*2], bb1 = ((float4*)bues)[cp*2 + 1];
        acc2[0] = pk2(bb0.x, bb0.y); acc2[1] = pk2(bb0.z, bb0.w);
        acc2[2] = pk2(bb1.x, bb1.y); acc2[3] = pk2(bb1.z, bb1.w);
        for (int k4 = 0; k4 < 32; k4++) {
            float4 a4 = As4[r*33 + k4];
#pragma unroll
            for (int kk = 0; kk < 4; kk++) {
                float a = ((float*)&a4)[kk];
                ull pa = pk2(a, a);
                int k = k4*4 + kk;
                U2 w0, w1;
                w0.f = Ws4[k*4 + cp*2];
                w1.f = Ws4[k*4 + cp*2 + 1];
                acc2[0] = f2(pa, w0.u.lo, acc2[0]);
                acc2[1] = f2(pa, w0.u.hi, acc2[1]);
                acc2[2] = f2(pa, w1.u.lo, acc2[2]);
                acc2[3] = f2(pa, w1.u.hi, acc2[3]);
            }
        }
        float2 r0_ = up2(acc2[0]), r1_ = up2(acc2[1]), r2_ = up2(acc2[2]), r3_ = up2(acc2[3]);
        ((float4*)out_edge)[(size_t)(e0 + r)*4 + cp*2]     = make_float4(r0_.x, r0_.y, r1_.x, r1_.y);
        ((float4*)out_edge)[(size_t)(e0 + r)*4 + cp*2 + 1] = make_float4(r2_.x, r2_.y, r3_.x, r3_.y);
    }
}

// ============ pass 2: exp weights, den, weighted value aggregation ============
__global__ void edge_attn(const int* __restrict__ ei) {
    int w = threadIdx.x >> 5, lane = threadIdx.x & 31;
    int e = blockIdx.x * 8 + w;
    int i = ei[e], j = ei[Ee + e];
    float ex = 0.f;
    if (lane < 4) {
        float s = g_scores[(size_t)e*4 + lane];
        float m = g_smax[i*4 + lane];
        ex = expf(s - m);
        atomicAdd(&g_den[i*4 + lane], ex);
    }
    float exh = __shfl_sync(0xffffffffu, ex, lane >> 3);
    float4 v4 = ((const float4*)g_val)[(size_t)j*32 + lane];
    float* base = &g_numer[(size_t)i*128 + lane*4];
    asm volatile("red.global.add.v4.f32 [%0], {%1,%2,%3,%4};"
                 :: "l"(base), "f"(exh*v4.x), "f"(exh*v4.y), "f"(exh*v4.z), "f"(exh*v4.w)
                 : "memory");
}

// ---------------- GraphNorm apply (output pass), float4-vectorized ----------------
__global__ void k_norm4(const float* __restrict__ w_, const float* __restrict__ b_,
                        const float* __restrict__ a_, const int* __restrict__ batch,
                        const float* __restrict__ X, float* __restrict__ Y, int statoff) {
    int idx = blockIdx.x*256 + threadIdx.x;
    if (idx >= Nn*32) return;
    int n = idx >> 5, q = idx & 31;
    int b = batch[n];
    float rc = 1.f / fmaxf(g_stats[4*Gg*Hh + b], 1.f);
    float4 s1 = *(const float4*)&g_stats[statoff + b*Hh + q*4];
    float4 s2 = *(const float4*)&g_stats[statoff + Gg*Hh + b*Hh + q*4];
    float4 x = ((const float4*)X)[(size_t)n*32 + q];
    float4 y = gnorm4(x, s1, s2, rc,
                      ((const float4*)a_)[q], ((const float4*)w_)[q], ((const float4*)b_)[q]);
    ((float4*)Y)[(size_t)n*32 + q] = y;
}

// ---------------- launch ----------------
extern "C" void kernel_launch(void* const* d_in, const int* in_sizes, int n_in,
                              void* d_out, int out_size) {
    const float* node = (const float*)d_in[0];
    const float* edge = (const float*)d_in[1];
    const float* coords = (const float*)d_in[2];
    const float* Ws = (const float*)d_in[3];  const float* bs = (const float*)d_in[4];
    const float* Wd = (const float*)d_in[5];  const float* bd = (const float*)d_in[6];
    const float* Wv = (const float*)d_in[7];  const float* bv = (const float*)d_in[8];
    const float* We1 = (const float*)d_in[9]; const float* be1 = (const float*)d_in[10];
    const float* We2 = (const float*)d_in[11];const float* be2 = (const float*)d_in[12];
    const float* Wun = (const float*)d_in[13];const float* bun = (const float*)d_in[14];
    const float* Wue = (const float*)d_in[15];const float* bue = (const float*)d_in[16];
    const float* Wg  = (const float*)d_in[17];const float* bg  = (const float*)d_in[18];
    const float* Wf1 = (const float*)d_in[19];const float* bf1 = (const float*)d_in[20];
    const float* Wf2 = (const float*)d_in[21];const float* bf2 = (const float*)d_in[22];
    const float* gn1w = (const float*)d_in[23];
    const float* gn1b = (const float*)d_in[24];
    const float* gn1a = (const float*)d_in[25];
    const float* gn2w = (const float*)d_in[26];
    const float* gn2b = (const float*)d_in[27];
    const float* gn2a = (const float*)d_in[28];
    const int* ei = (const int*)d_in[29];
    const int* batch = (const int*)d_in[30];

    float* out = (float*)d_out;
    float* out_n2 = out;
    float* out_edge = out + (size_t)Nn*Hh;
    float* out_coords = out + (size_t)Nn*Hh + (size_t)Ee*16;

    size_t gemm_smem = (8192 + 128*132) * sizeof(float);                  // 100352
    size_t ef_smem   = (8192 + 16896 + 2560 + 512 + 128 + 128 + 16) * sizeof(float)
                     + 256 * sizeof(int);                                  // 114752
    cudaFuncSetAttribute(gemm_proj,    cudaFuncAttributeMaxDynamicSharedMemorySize, (int)gemm_smem);
    cudaFuncSetAttribute(gemm_nngate,  cudaFuncAttributeMaxDynamicSharedMemorySize, (int)gemm_smem);
    cudaFuncSetAttribute(gemm_fix_h2,  cudaFuncAttributeMaxDynamicSharedMemorySize, (int)gemm_smem);
    cudaFuncSetAttribute(edge_fused,   cudaFuncAttributeMaxDynamicSharedMemorySize, (int)ef_smem);

    float *p_src,*p_dst,*p_val,*p_h2;
    void* p;
    cudaGetSymbolAddress(&p, g_src); p_src = (float*)p;
    cudaGetSymbolAddress(&p, g_dst); p_dst = (float*)p;
    cudaGetSymbolAddress(&p, g_val); p_val = (float*)p;
    cudaGetSymbolAddress(&p, g_h2); p_h2 = (float*)p;

    cudaGetSymbolAddress(&p, g_smax);  cudaMemsetAsync(p, 0, sizeof(float)*Nn*NHh, 0);
    cudaGetSymbolAddress(&p, g_den);   cudaMemsetAsync(p, 0, sizeof(float)*Nn*NHh, 0);
    cudaGetSymbolAddress(&p, g_numer); cudaMemsetAsync(p, 0, sizeof(float)*Nn*Hh, 0);
    cudaGetSymbolAddress(&p, g_stats); cudaMemsetAsync(p, 0, sizeof(float)*(4*Gg*Hh + Gg), 0);

    int vecGrid  = (Nn*32 + 255) / 256;     // 3750
    int edgeWGrid = Ee / 8;                 // 60000
    int edgeFGrid = Ee / 128;               // 3750

    // node projections + gate-part: 4*NTILES independent (tile, weight) tasks
    gemm_proj<<<4*NTILES, 256, gemm_smem>>>(node, Ws, bs, p_src, Wd, bd, p_dst,
                                            Wv, bv, p_val, Wg, bg);

    // fused edge pipeline
    edge_fused<<<edgeFGrid, 256, ef_smem>>>(edge, coords, We1, be1, We2, be2,
                                            Wue, bue, ei, out_edge);

    // softmax + aggregation
    edge_attn<<<edgeWGrid, 256>>>(ei);

    // merged: nodenew GEMM + gate (1 GEMM + precomputed gpart) + h1 + stats1
    gemm_nngate<<<NTILES, 256, gemm_smem>>>(node, Wun, bun, Wg, batch);

    // fix_node with inline norm1 + h2 + stats2
    gemm_fix_h2<<<NTILES, 256, gemm_smem>>>(Wf1, bf1, Wf2, bf2, gn1w, gn1b, gn1a, batch);

    // norm2 -> output
    k_norm4<<<vecGrid, 256>>>(gn2w, gn2b, gn2a, batch, p_h2, out_n2, 2*Gg*Hh);

    // coords pass-through
    cudaMemcpyAsync(out_coords, coords, sizeof(float)*Nn*3, cudaMemcpyDeviceToDevice, 0);

    (void)in_sizes; (void)n_in; (void)out_size;
}

// round 17
// speedup vs baseline: 1.0803x; 1.0689x over previous
#include <cuda_runtime.h>
#include <math.h>

#define Nn 30000
#define Ee 480000
#define Hh 128
#define NHh 4
#define Gg 64
#define EPSf 1e-5f
#define NTILES 235

typedef unsigned long long ull;
typedef unsigned int uint;
union U2 { float4 f; struct { ull lo, hi; } u; };

__device__ __forceinline__ ull pk2(float x, float y) {
    ull r; asm("mov.b64 %0,{%1,%2};" : "=l"(r) : "f"(x), "f"(y)); return r;
}
__device__ __forceinline__ ull f2(ull a, ull b, ull c) {
    ull d; asm("fma.rn.f32x2 %0,%1,%2,%3;" : "=l"(d) : "l"(a), "l"(b), "l"(c)); return d;
}
__device__ __forceinline__ float2 up2(ull v) {
    float2 f; asm("mov.b64 {%0,%1},%2;" : "=f"(f.x), "=f"(f.y) : "l"(v)); return f;
}
__device__ __forceinline__ void red4(float* p, float4 v) {
    asm volatile("red.global.add.v4.f32 [%0],{%1,%2,%3,%4};"
                 :: "l"(p), "f"(v.x), "f"(v.y), "f"(v.z), "f"(v.w) : "memory");
}
__device__ __forceinline__ void red1(float* p, float v) {
    asm volatile("red.global.add.f32 [%0],%1;" :: "l"(p), "f"(v) : "memory");
}
__device__ __forceinline__ float tf32r(float x) {
    uint r; asm("cvt.rna.tf32.f32 %0, %1;" : "=r"(r) : "f"(x));
    return __uint_as_float(r);
}
__device__ __forceinline__ void mma_tf32(float d[4], uint a0, uint a1, uint a2, uint a3,
                                         uint b0, uint b1) {
    asm volatile(
        "mma.sync.aligned.m16n8k8.row.col.f32.tf32.tf32.f32 "
        "{%0,%1,%2,%3}, {%4,%5,%6,%7}, {%8,%9}, {%0,%1,%2,%3};"
        : "+f"(d[0]), "+f"(d[1]), "+f"(d[2]), "+f"(d[3])
        : "r"(a0), "r"(a1), "r"(a2), "r"(a3), "r"(b0), "r"(b1));
}

// ---------------- scratch (device globals) ----------------
__device__ float g_src[Nn*Hh];
__device__ float g_dst[Nn*Hh];
__device__ float g_val[Nn*Hh];
__device__ float g_gpart[Nn*Hh];     // node@Wg2 + bg (precomputed)
__device__ float g_scores[(size_t)Ee*NHh];
__device__ float g_smax[Nn*NHh];
__device__ float g_den[Nn*NHh];
__device__ float g_numer[Nn*Hh];
__device__ float g_nodenew[Nn*Hh];
__device__ float g_gate[Nn*Hh];
__device__ float g_h1[Nn*Hh];
__device__ float g_h2[Nn*Hh];
// [0,GH) sum1 | [GH,2GH) sq1 | [2GH,3GH) sum2 | [3GH,4GH) sq2 | [4GH,4GH+G) cnt
__device__ float g_stats[4*Gg*Hh + Gg];

// load half of a 128x128 B (64 K-rows) de-interleaved into Bs (2048 float4)
__device__ __forceinline__ void load_Bhalf(float4* Bs4, const float4* B4half, int tid) {
#pragma unroll
    for (int it = 0; it < 8; it++) {
        int v = tid + 256*it;
        int c4 = v & 31;
        Bs4[(v & ~31) | (((c4 & 1) << 4) | (c4 >> 1))] = B4half[v];
    }
}

// combined-weight B-half loader: z = Wa + sgn*Wb
__device__ __forceinline__ void load_Bhalf_comb(float4* Bs4, const float4* Wa,
                                                const float4* Wb, float sgn, int tid) {
#pragma unroll
    for (int it = 0; it < 8; it++) {
        int v = tid + 256*it;
        int c4 = v & 31;
        float4 x = Wa[v], y = Wb[v];
        float4 z = make_float4(x.x + sgn*y.x, x.y + sgn*y.y, x.z + sgn*y.z, x.w + sgn*y.w);
        Bs4[(v & ~31) | (((c4 & 1) << 4) | (c4 >> 1))] = z;
    }
}

// 16 k4-steps of the 8x8 f32x2 GEMM inner loop
__device__ __forceinline__ void gemm_half(ull acc[8][4], const float4* Bs4, const float4* As4,
                                          int k4_0, int cg, int r0) {
    for (int k4 = k4_0; k4 < k4_0 + 16; k4++) {
        float4 a4[8];
#pragma unroll
        for (int rr = 0; rr < 8; rr++) a4[rr] = As4[(r0 + rr)*33 + k4];
#pragma unroll
        for (int kk = 0; kk < 4; kk++) {
            U2 w0, w1;
            w0.f = Bs4[((k4 - k4_0)*4 + kk)*32 + cg];
            w1.f = Bs4[((k4 - k4_0)*4 + kk)*32 + 16 + cg];
#pragma unroll
            for (int rr = 0; rr < 8; rr++) {
                float a = ((float*)&a4[rr])[kk];
                ull pa = pk2(a, a);
                acc[rr][0] = f2(pa, w0.u.lo, acc[rr][0]);
                acc[rr][1] = f2(pa, w0.u.hi, acc[rr][1]);
                acc[rr][2] = f2(pa, w1.u.lo, acc[rr][2]);
                acc[rr][3] = f2(pa, w1.u.hi, acc[rr][3]);
            }
        }
    }
}

__device__ __forceinline__ void load_Atile(float4* As4, const float4* A4, int row0, int tid) {
#pragma unroll
    for (int it = 0; it < 16; it++) {
        int v = tid + 256*it;
        int r = v >> 5, q = v & 31;
        As4[r*33 + q] = (row0 + r < Nn) ? A4[(size_t)(row0 + r)*32 + q]
                                        : make_float4(0.f,0.f,0.f,0.f);
    }
}

// GraphNorm on a float4 (must match everywhere for consistency)
__device__ __forceinline__ float4 gnorm4(float4 x, float4 s1, float4 s2, float rc,
                                         float4 a, float4 w, float4 bb) {
    float4 y;
    {
        float mean = s1.x*rc, m2 = s2.x*rc;
        float var = m2 + mean*mean*(a.x*a.x - 2.f*a.x);
        y.x = w.x * (x.x - a.x*mean) * rsqrtf(var + EPSf) + bb.x;
    }
    {
        float mean = s1.y*rc, m2 = s2.y*rc;
        float var = m2 + mean*mean*(a.y*a.y - 2.f*a.y);
        y.y = w.y * (x.y - a.y*mean) * rsqrtf(var + EPSf) + bb.y;
    }
    {
        float mean = s1.z*rc, m2 = s2.z*rc;
        float var = m2 + mean*mean*(a.z*a.z - 2.f*a.z);
        y.z = w.z * (x.z - a.z*mean) * rsqrtf(var + EPSf) + bb.z;
    }
    {
        float mean = s1.w*rc, m2 = s2.w*rc;
        float var = m2 + mean*mean*(a.w*a.w - 2.f*a.w);
        y.w = w.w * (x.w - a.w*mean) * rsqrtf(var + EPSf) + bb.w;
    }
    return y;
}

// ============ projection: task = (tile, weight); grid = 4*NTILES ============
__global__ __launch_bounds__(256, 2) void gemm_proj(
        const float* __restrict__ A,
        const float* __restrict__ B0, const float* __restrict__ b0, float* __restrict__ C0,
        const float* __restrict__ B1, const float* __restrict__ b1, float* __restrict__ C1,
        const float* __restrict__ B2, const float* __restrict__ b2, float* __restrict__ C2,
        const float* __restrict__ Wg, const float* __restrict__ bg) {
    extern __shared__ float sm[];
    float4* Bs4 = (float4*)sm;
    float4* As4 = (float4*)(sm + 8192);
    int tid = threadIdx.x;
    int w = blockIdx.x / NTILES;
    int row0 = (blockIdx.x % NTILES) * 128;
    const float4* Wg4 = (const float4*)Wg;
    const float* bias = (w == 0) ? b0 : (w == 1) ? b1 : (w == 2) ? b2 : bg;
    float* C;
    { void* p; asm("mov.u64 %0, g_gpart;" : "=l"(p));
      C = (w == 0) ? C0 : (w == 1) ? C1 : (w == 2) ? C2 : (float*)p; }

    load_Atile(As4, (const float4*)A, row0, tid);
    if (w < 3) {
        const float4* B4 = (const float4*)((w == 0) ? B0 : (w == 1) ? B1 : B2);
        load_Bhalf(Bs4, B4, tid);
    } else {
        load_Bhalf_comb(Bs4, Wg4 + 4096, Wg4 + 8192, -1.f, tid);
    }
    __syncthreads();
    int rg = tid >> 4, cg = tid & 15;
    int r0 = rg * 8;
    ull acc[8][4];
#pragma unroll
    for (int rr = 0; rr < 8; rr++) { acc[rr][0]=0; acc[rr][1]=0; acc[rr][2]=0; acc[rr][3]=0; }
    gemm_half(acc, Bs4, As4, 0, cg, r0);
    __syncthreads();
    if (w < 3) {
        const float4* B4 = (const float4*)((w == 0) ? B0 : (w == 1) ? B1 : B2);
        load_Bhalf(Bs4, B4 + 2048, tid);
    } else {
        load_Bhalf_comb(Bs4, Wg4 + 4096 + 2048, Wg4 + 8192 + 2048, -1.f, tid);
    }
    __syncthreads();
    gemm_half(acc, Bs4, As4, 16, cg, r0);
    float4 bi0 = ((const float4*)bias)[cg*2];
    float4 bi1 = ((const float4*)bias)[cg*2 + 1];
#pragma unroll
    for (int rr = 0; rr < 8; rr++) {
        int r = row0 + r0 + rr;
        if (r < Nn) {
            float2 f0 = up2(acc[rr][0]), f1 = up2(acc[rr][1]);
            float2 f2_ = up2(acc[rr][2]), f3 = up2(acc[rr][3]);
            ((float4*)C)[(size_t)r*32 + cg*2]     = make_float4(f0.x+bi0.x, f0.y+bi0.y, f1.x+bi0.z, f1.y+bi0.w);
            ((float4*)C)[(size_t)r*32 + cg*2 + 1] = make_float4(f2_.x+bi1.x, f2_.y+bi1.y, f3.x+bi1.z, f3.y+bi1.w);
        }
    }
}

// ============ merged: nodenew GEMM + gate (1 GEMM + gpart) + sigmoid + h1 + stats1 ============
__global__ __launch_bounds__(256, 2) void gemm_nngate(
        const float* __restrict__ node,
        const float* __restrict__ Wun, const float* __restrict__ bun,
        const float* __restrict__ Wg,
        const int* __restrict__ batch) {
    extern __shared__ float sm[];
    float4* Bs4 = (float4*)sm;
    float4* As4 = (float4*)(sm + 8192);
    int tid = threadIdx.x;
    int row0 = blockIdx.x * 128;
    int rg = tid >> 4, cg = tid & 15;
    int r0 = rg * 8;
    const float4* Wg4 = (const float4*)Wg;

    // ---- PHASE A: nodenew = (numer/den)@Wun + bun ----
#pragma unroll
    for (int it = 0; it < 16; it++) {
        int v = tid + 256*it;
        int r = v >> 5, q = v & 31;
        float4 x = make_float4(0.f,0.f,0.f,0.f);
        int row = row0 + r;
        if (row < Nn) {
            x = ((const float4*)g_numer)[(size_t)row*32 + q];
            float dv = g_den[row*4 + (q >> 3)];
            float inv = (dv > 0.f) ? __fdividef(1.f, dv) : 0.f;
            x.x *= inv; x.y *= inv; x.z *= inv; x.w *= inv;
        }
        As4[r*33 + q] = x;
    }
    ull acc[8][4];
#pragma unroll
    for (int rr = 0; rr < 8; rr++) { acc[rr][0]=0; acc[rr][1]=0; acc[rr][2]=0; acc[rr][3]=0; }
    load_Bhalf(Bs4, (const float4*)Wun, tid);
    __syncthreads();
    gemm_half(acc, Bs4, As4, 0, cg, r0);
    __syncthreads();
    load_Bhalf(Bs4, (const float4*)Wun + 2048, tid);
    __syncthreads();
    gemm_half(acc, Bs4, As4, 16, cg, r0);
    __syncthreads();
    {
        float4 bi0 = ((const float4*)bun)[cg*2];
        float4 bi1 = ((const float4*)bun)[cg*2 + 1];
#pragma unroll
        for (int rr = 0; rr < 8; rr++) {
            int r = row0 + r0 + rr;
            float2 f0 = up2(acc[rr][0]), f1 = up2(acc[rr][1]);
            float2 f2_ = up2(acc[rr][2]), f3 = up2(acc[rr][3]);
            float4 v0 = make_float4(f0.x+bi0.x, f0.y+bi0.y, f1.x+bi0.z, f1.y+bi0.w);
            float4 v1 = make_float4(f2_.x+bi1.x, f2_.y+bi1.y, f3.x+bi1.z, f3.y+bi1.w);
            As4[(r0 + rr)*33 + cg*2]     = v0;
            As4[(r0 + rr)*33 + cg*2 + 1] = v1;
            if (r < Nn) {
                ((float4*)g_nodenew)[(size_t)r*32 + cg*2]     = v0;
                ((float4*)g_nodenew)[(size_t)r*32 + cg*2 + 1] = v1;
            }
        }
    }
    __syncthreads();

    // ---- PHASE B: accG = nodenew(As) @ (Wg[0:H] + Wg[2H:3H]) ----
#pragma unroll
    for (int rr = 0; rr < 8; rr++) { acc[rr][0]=0; acc[rr][1]=0; acc[rr][2]=0; acc[rr][3]=0; }
    load_Bhalf_comb(Bs4, Wg4, Wg4 + 8192, 1.f, tid);
    __syncthreads();
    gemm_half(acc, Bs4, As4, 0, cg, r0);
    __syncthreads();
    load_Bhalf_comb(Bs4, Wg4 + 2048, Wg4 + 8192 + 2048, 1.f, tid);
    __syncthreads();
    gemm_half(acc, Bs4, As4, 16, cg, r0);

    // ---- EPILOGUE ----
#pragma unroll
    for (int rr = 0; rr < 8; rr++) {
        int r = row0 + r0 + rr;
        if (r < Nn) {
            float4 gp0 = ((const float4*)g_gpart)[(size_t)r*32 + cg*2];
            float4 gp1 = ((const float4*)g_gpart)[(size_t)r*32 + cg*2 + 1];
            float2 f0 = up2(acc[rr][0]), f1 = up2(acc[rr][1]);
            float2 f2_ = up2(acc[rr][2]), f3 = up2(acc[rr][3]);
            float4 v0 = make_float4(f0.x+gp0.x, f0.y+gp0.y, f1.x+gp0.z, f1.y+gp0.w);
            float4 v1 = make_float4(f2_.x+gp1.x, f2_.y+gp1.y, f3.x+gp1.z, f3.y+gp1.w);
            v0.x = 1.f/(1.f+expf(-v0.x)); v0.y = 1.f/(1.f+expf(-v0.y));
            v0.z = 1.f/(1.f+expf(-v0.z)); v0.w = 1.f/(1.f+expf(-v0.w));
            v1.x = 1.f/(1.f+expf(-v1.x)); v1.y = 1.f/(1.f+expf(-v1.y));
            v1.z = 1.f/(1.f+expf(-v1.z)); v1.w = 1.f/(1.f+expf(-v1.w));
            ((float4*)g_gate)[(size_t)r*32 + cg*2]     = v0;
            ((float4*)g_gate)[(size_t)r*32 + cg*2 + 1] = v1;
            float4 nn0 = As4[(r0 + rr)*33 + cg*2];
            float4 nn1 = As4[(r0 + rr)*33 + cg*2 + 1];
            float4 nd0 = ((const float4*)node)[(size_t)r*32 + cg*2];
            float4 nd1 = ((const float4*)node)[(size_t)r*32 + cg*2 + 1];
            float4 h0 = make_float4(v0.x*nn0.x+nd0.x, v0.y*nn0.y+nd0.y,
                                    v0.z*nn0.z+nd0.z, v0.w*nn0.w+nd0.w);
            float4 h1v = make_float4(v1.x*nn1.x+nd1.x, v1.y*nn1.y+nd1.y,
                                     v1.z*nn1.z+nd1.z, v1.w*nn1.w+nd1.w);
            ((float4*)g_h1)[(size_t)r*32 + cg*2]     = h0;
            ((float4*)g_h1)[(size_t)r*32 + cg*2 + 1] = h1v;
            int b = batch[r];
            red4(&g_stats[b*Hh + cg*8],     h0);
            red4(&g_stats[b*Hh + cg*8 + 4], h1v);
            red4(&g_stats[Gg*Hh + b*Hh + cg*8],
                 make_float4(h0.x*h0.x, h0.y*h0.y, h0.z*h0.z, h0.w*h0.w));
            red4(&g_stats[Gg*Hh + b*Hh + cg*8 + 4],
                 make_float4(h1v.x*h1v.x, h1v.y*h1v.y, h1v.z*h1v.z, h1v.w*h1v.w));
            if (cg == 0) red1(&g_stats[4*Gg*Hh + b], 1.f);
        }
    }
}

// ============ fused fix_node with inline norm1 (UNCHANGED) ============
__global__ __launch_bounds__(256, 2) void gemm_fix_h2(
        const float* __restrict__ Wf1, const float* __restrict__ bf1,
        const float* __restrict__ Wf2, const float* __restrict__ bf2,
        const float* __restrict__ gn1w, const float* __restrict__ gn1b,
        const float* __restrict__ gn1a, const int* __restrict__ batch) {
    extern __shared__ float sm[];
    float4* Bs4 = (float4*)sm;
    float4* As4 = (float4*)(sm + 8192);
    int tid = threadIdx.x;
    int row0 = blockIdx.x * 128;
    int rg = tid >> 4, cg = tid & 15;
    int r0 = rg * 8;

#pragma unroll
    for (int it = 0; it < 16; it++) {
        int v = tid + 256*it;
        int r = v >> 5, q = v & 31;
        int row = row0 + r;
        float4 x = make_float4(0.f,0.f,0.f,0.f);
        if (row < Nn) {
            x = ((const float4*)g_h1)[(size_t)row*32 + q];
            int b = batch[row];
            float rc = 1.f / fmaxf(g_stats[4*Gg*Hh + b], 1.f);
            float4 s1 = *(const float4*)&g_stats[b*Hh + q*4];
            float4 s2 = *(const float4*)&g_stats[Gg*Hh + b*Hh + q*4];
            x = gnorm4(x, s1, s2, rc,
                       ((const float4*)gn1a)[q], ((const float4*)gn1w)[q],
                       ((const float4*)gn1b)[q]);
        }
        As4[r*33 + q] = x;
    }
    ull acc[8][4];
#pragma unroll
    for (int rr = 0; rr < 8; rr++) { acc[rr][0]=0; acc[rr][1]=0; acc[rr][2]=0; acc[rr][3]=0; }
    load_Bhalf(Bs4, (const float4*)Wf1, tid);
    __syncthreads();
    gemm_half(acc, Bs4, As4, 0, cg, r0);
    __syncthreads();
    load_Bhalf(Bs4, (const float4*)Wf1 + 2048, tid);
    __syncthreads();
    gemm_half(acc, Bs4, As4, 16, cg, r0);
    __syncthreads();
    {
        float4 bi0 = ((const float4*)bf1)[cg*2];
        float4 bi1 = ((const float4*)bf1)[cg*2 + 1];
#pragma unroll
        for (int rr = 0; rr < 8; rr++) {
            float2 f0 = up2(acc[rr][0]), f1 = up2(acc[rr][1]);
            float2 f2_ = up2(acc[rr][2]), f3 = up2(acc[rr][3]);
            float v[8] = { f0.x+bi0.x, f0.y+bi0.y, f1.x+bi0.z, f1.y+bi0.w,
                           f2_.x+bi1.x, f2_.y+bi1.y, f3.x+bi1.z, f3.y+bi1.w };
#pragma unroll
            for (int q = 0; q < 8; q++) v[q] = v[q] > 0.f ? v[q] : 0.01f*v[q];
            As4[(r0 + rr)*33 + cg*2]     = make_float4(v[0], v[1], v[2], v[3]);
            As4[(r0 + rr)*33 + cg*2 + 1] = make_float4(v[4], v[5], v[6], v[7]);
        }
    }
    __syncthreads();
#pragma unroll
    for (int rr = 0; rr < 8; rr++) { acc[rr][0]=0; acc[rr][1]=0; acc[rr][2]=0; acc[rr][3]=0; }
    load_Bhalf(Bs4, (const float4*)Wf2, tid);
    __syncthreads();
    gemm_half(acc, Bs4, As4, 0, cg, r0);
    __syncthreads();
    load_Bhalf(Bs4, (const float4*)Wf2 + 2048, tid);
    __syncthreads();
    gemm_half(acc, Bs4, As4, 16, cg, r0);

    float4 bi0 = ((const float4*)bf2)[cg*2];
    float4 bi1 = ((const float4*)bf2)[cg*2 + 1];
#pragma unroll
    for (int rr = 0; rr < 8; rr++) {
        int r = row0 + r0 + rr;
        if (r < Nn) {
            float2 f0 = up2(acc[rr][0]), f1 = up2(acc[rr][1]);
            float2 f2_ = up2(acc[rr][2]), f3 = up2(acc[rr][3]);
            float4 x0 = make_float4(f0.x+bi0.x, f0.y+bi0.y, f1.x+bi0.z, f1.y+bi0.w);
            float4 x1 = make_float4(f2_.x+bi1.x, f2_.y+bi1.y, f3.x+bi1.z, f3.y+bi1.w);
            int b = batch[r];
            float rc = 1.f / fmaxf(g_stats[4*Gg*Hh + b], 1.f);
            int q0 = cg*2, q1 = cg*2 + 1;
            float4 h1a = ((const float4*)g_h1)[(size_t)r*32 + q0];
            float4 h1b = ((const float4*)g_h1)[(size_t)r*32 + q1];
            float4 n10 = gnorm4(h1a, *(const float4*)&g_stats[b*Hh + q0*4],
                                *(const float4*)&g_stats[Gg*Hh + b*Hh + q0*4], rc,
                                ((const float4*)gn1a)[q0], ((const float4*)gn1w)[q0],
                                ((const float4*)gn1b)[q0]);
            float4 n11 = gnorm4(h1b, *(const float4*)&g_stats[b*Hh + q1*4],
                                *(const float4*)&g_stats[Gg*Hh + b*Hh + q1*4], rc,
                                ((const float4*)gn1a)[q1], ((const float4*)gn1w)[q1],
                                ((const float4*)gn1b)[q1]);
            float4 gg0 = ((const float4*)g_gate)[(size_t)r*32 + q0];
            float4 gg1 = ((const float4*)g_gate)[(size_t)r*32 + q1];
            float4 h0 = make_float4(gg0.x*x0.x+n10.x, gg0.y*x0.y+n10.y,
                                    gg0.z*x0.z+n10.z, gg0.w*x0.w+n10.w);
            float4 h1v = make_float4(gg1.x*x1.x+n11.x, gg1.y*x1.y+n11.y,
                                     gg1.z*x1.z+n11.z, gg1.w*x1.w+n11.w);
            ((float4*)g_h2)[(size_t)r*32 + q0] = h0;
            ((float4*)g_h2)[(size_t)r*32 + q1] = h1v;
            red4(&g_stats[2*Gg*Hh + b*Hh + cg*8],     h0);
            red4(&g_stats[2*Gg*Hh + b*Hh + cg*8 + 4], h1v);
            red4(&g_stats[3*Gg*Hh + b*Hh + cg*8],
                 make_float4(h0.x*h0.x, h0.y*h0.y, h0.z*h0.z, h0.w*h0.w));
            red4(&g_stats[3*Gg*Hh + b*Hh + cg*8 + 4],
                 make_float4(h1v.x*h1v.x, h1v.y*h1v.y, h1v.z*h1v.z, h1v.w*h1v.w));
        }
    }
}

// ============ fused edge kernel: stage1 FFMA + GEMM2 via mma.sync tf32 ============
// smem: Bs 8448 (We1+xs -> We2 plain tf32 halves stride 132 -> Wue) | As 128x132 |
//       score_s 512 | be1s 128 | be2s 128 | bues 16 | is_ 128 | js_ 128
__global__ __launch_bounds__(256, 2) void edge_fused(
        const float* __restrict__ edge, const float* __restrict__ coords,
        const float* __restrict__ We1, const float* __restrict__ be1,
        const float* __restrict__ We2, const float* __restrict__ be2,
        const float* __restrict__ Wue, const float* __restrict__ bue,
        const int* __restrict__ ei, float* __restrict__ out_edge) {
    extern __shared__ float sm[];
    float* Bs      = sm;                 // 8448
    float* As      = Bs + 8448;          // 16896
    float* score_s = As + 16896;         // 512
    float* be1s    = score_s + 512;      // 128
    float* be2s    = be1s + 128;         // 128
    float* bues    = be2s + 128;         // 16
    int*   is_     = (int*)(bues + 16);  // 128
    int*   js_     = is_ + 128;          // 128
    float* xs      = Bs + 2560;          // 2560 floats inside Bs slack (We1 uses 2176)

    int tid = threadIdx.x;
    int e0 = blockIdx.x * 128;
    float4* Bs4 = (float4*)Bs;
    float4* As4 = (float4*)As;
    float4* xs4 = (float4*)xs;
    float4* Ws4 = (float4*)Bs;

    if (tid < 128) { is_[tid] = ei[e0 + tid]; js_[tid] = ei[Ee + e0 + tid]; }
    for (int v = tid; v < 17*128; v += 256) Bs[v] = We1[v];
    if (tid < 128) { be1s[tid] = be1[tid]; be2s[tid] = be2[tid]; }
    if (tid < 16) bues[tid] = bue[tid];
    score_s[tid] = 0.f; score_s[tid + 256] = 0.f;
    {
        const float4* E4 = (const float4*)edge;
#pragma unroll
        for (int it = 0; it < 2; it++) {
            int v = tid + 256*it;
            int r = v >> 2, q = v & 3;
            xs4[r*5 + q] = E4[(size_t)(e0 + r)*4 + q];
        }
    }
    __syncthreads();
    if (tid < 128) {
        int i = is_[tid], j = js_[tid];
        float dx = coords[3*i]   - coords[3*j];
        float dy = coords[3*i+1] - coords[3*j+1];
        float dz = coords[3*i+2] - coords[3*j+2];
        xs[tid*20 + 16] = sqrtf(dx*dx + dy*dy + dz*dz + 1e-12f) * 0.1f;
    }
    __syncthreads();

    // ---- stage 1: tmp = leaky([edge,dist] @ We1 + be1), stored tf32-rounded ----
    {
        int rg = tid >> 4, cg = tid & 15;
        int r0 = rg * 8;
        ull acc1[8][4];
        float4 b0 = ((float4*)be1s)[cg*2], b1 = ((float4*)be1s)[cg*2 + 1];
        ull i0 = pk2(b0.x,b0.y), i1 = pk2(b0.z,b0.w), i2 = pk2(b1.x,b1.y), i3 = pk2(b1.z,b1.w);
#pragma unroll
        for (int rr = 0; rr < 8; rr++) { acc1[rr][0]=i0; acc1[rr][1]=i1; acc1[rr][2]=i2; acc1[rr][3]=i3; }
#pragma unroll
        for (int k = 0; k < 17; k++) {
            U2 w0, w1;
            w0.f = Bs4[k*32 + cg*2];
            w1.f = Bs4[k*32 + cg*2 + 1];
#pragma unroll
            for (int rr = 0; rr < 8; rr++) {
                float a = xs[(r0 + rr)*20 + k];
                ull pa = pk2(a, a);
                acc1[rr][0] = f2(pa, w0.u.lo, acc1[rr][0]);
                acc1[rr][1] = f2(pa, w0.u.hi, acc1[rr][1]);
                acc1[rr][2] = f2(pa, w1.u.lo, acc1[rr][2]);
                acc1[rr][3] = f2(pa, w1.u.hi, acc1[rr][3]);
            }
        }
#pragma unroll
        for (int rr = 0; rr < 8; rr++) {
            float2 f0 = up2(acc1[rr][0]), f1 = up2(acc1[rr][1]);
            float2 f2_ = up2(acc1[rr][2]), f3 = up2(acc1[rr][3]);
            float v[8] = { f0.x, f0.y, f1.x, f1.y, f2_.x, f2_.y, f3.x, f3.y };
#pragma unroll
            for (int q = 0; q < 8; q++) {
                v[q] = v[q] > 0.f ? v[q] : 0.01f*v[q];
                v[q] = tf32r(v[q]);
            }
            As4[(r0 + rr)*33 + cg*2]     = make_float4(v[0], v[1], v[2], v[3]);
            As4[(r0 + rr)*33 + cg*2 + 1] = make_float4(v[4], v[5], v[6], v[7]);
        }
    }
    __syncthreads();

    // ---- GEMM2 via mma.sync m16n8k8 tf32: e = tmp @ We2 + be2 ----
    int wid = tid >> 5, lane = tid & 31;
    int g = lane >> 2, c = lane & 3;
    int mrow = wid*16 + g;
    float acc[16][4];
#pragma unroll
    for (int t = 0; t < 16; t++) {
        float b0v = be2s[t*8 + c*2], b1v = be2s[t*8 + c*2 + 1];
        acc[t][0] = b0v; acc[t][1] = b1v; acc[t][2] = b0v; acc[t][3] = b1v;
    }
#pragma unroll
    for (int half = 0; half < 2; half++) {
        // load We2 half plain (stride 132 floats), tf32-rounded
        {
            const float4* W24 = (const float4*)We2 + half*2048;
#pragma unroll
            for (int it = 0; it < 8; it++) {
                int v = tid + 256*it;
                float4 x = W24[v];
                x.x = tf32r(x.x); x.y = tf32r(x.y); x.z = tf32r(x.z); x.w = tf32r(x.w);
                Bs4[(v >> 5)*33 + (v & 31)] = x;
            }
        }
        __syncthreads();
        int kb0 = half*64;
#pragma unroll
        for (int ks = 0; ks < 8; ks++) {
            int kb = ks*8;
            uint a0 = __float_as_uint(As[mrow*132 + kb0 + kb + c]);
            uint a1 = __float_as_uint(As[(mrow+8)*132 + kb0 + kb + c]);
            uint a2 = __float_as_uint(As[mrow*132 + kb0 + kb + c + 4]);
            uint a3 = __float_as_uint(As[(mrow+8)*132 + kb0 + kb + c + 4]);
#pragma unroll
            for (int t = 0; t < 16; t++) {
                uint b0 = __float_as_uint(Bs[(kb + c)*132 + t*8 + g]);
                uint b1 = __float_as_uint(Bs[(kb + c + 4)*132 + t*8 + g]);
                mma_tf32(acc[t], a0, a1, a2, a3, b0, b1);
            }
        }
        __syncthreads();
    }

    // ---- edge_result + scores + er->As (+ load Wue into Bs) ----
    {
        Ws4[tid]       = ((const float4*)Wue)[tid];
        Ws4[tid + 256] = ((const float4*)Wue)[tid + 256];
        const float inv = 0.17677669529663688f;  // 1/sqrt(32)
        int r1 = mrow, r2 = mrow + 8;
        int i1 = is_[r1], j1 = js_[r1];
        int i2 = is_[r2], j2 = js_[r2];
        float hs1[4] = {0.f,0.f,0.f,0.f}, hs2[4] = {0.f,0.f,0.f,0.f};
#pragma unroll
        for (int t = 0; t < 16; t++) {
            int col = t*8 + c*2;
            float2 sj1 = *(const float2*)&g_src[(size_t)j1*128 + col];
            float2 di1 = *(const float2*)&g_dst[(size_t)i1*128 + col];
            float2 sj2 = *(const float2*)&g_src[(size_t)j2*128 + col];
            float2 di2 = *(const float2*)&g_dst[(size_t)i2*128 + col];
            float e0 = di1.x*sj1.x*acc[t][0]*inv;
            float e1 = di1.y*sj1.y*acc[t][1]*inv;
            float e2 = di2.x*sj2.x*acc[t][2]*inv;
            float e3 = di2.y*sj2.y*acc[t][3]*inv;
            int h = t >> 2;
            hs1[h] += fabsf(e0) + fabsf(e1);
            hs2[h] += fabsf(e2) + fabsf(e3);
            *(float2*)&As[r1*132 + col] = make_float2(e0, e1);
            *(float2*)&As[r2*132 + col] = make_float2(e2, e3);
        }
#pragma unroll
        for (int h = 0; h < 4; h++) {
            hs1[h] += __shfl_xor_sync(0xffffffffu, hs1[h], 1);
            hs1[h] += __shfl_xor_sync(0xffffffffu, hs1[h], 2);
            hs2[h] += __shfl_xor_sync(0xffffffffu, hs2[h], 1);
            hs2[h] += __shfl_xor_sync(0xffffffffu, hs2[h], 2);
        }
        if (c == 0) {
#pragma unroll
            for (int h = 0; h < 4; h++) {
                score_s[r1*4 + h] = hs1[h];
                score_s[r2*4 + h] = hs2[h];
            }
        }
    }
    __syncthreads();

    // ---- scores out + smax atomicMax ----
#pragma unroll
    for (int t = 0; t < 2; t++) {
        int v = tid + 256*t;
        int r = v >> 2, h = v & 3;
        float s = score_s[v];
        g_scores[(size_t)(e0 + r)*4 + h] = s;
        atomicMax((int*)&g_smax[is_[r]*4 + h], __float_as_int(s));
    }

    // ---- edge_new = er @ Wue + bue (float4 As reads) ----
    {
        int r = tid >> 1, cp = tid & 1;
        ull acc2[4];
        float4 bb0 = ((float4*)bues)[cp*2], bb1 = ((float4*)bues)[cp*2 + 1];
        acc2[0] = pk2(bb0.x, bb0.y); acc2[1] = pk2(bb0.z, bb0.w);
        acc2[2] = pk2(bb1.x, bb1.y); acc2[3] = pk2(bb1.z, bb1.w);
        for (int k4 = 0; k4 < 32; k4++) {
            float4 a4 = As4[r*33 + k4];
#pragma unroll
            for (int kk = 0; kk < 4; kk++) {
                float a = ((float*)&a4)[kk];
                ull pa = pk2(a, a);
                int k = k4*4 + kk;
                U2 w0, w1;
                w0.f = Ws4[k*4 + cp*2];
                w1.f = Ws4[k*4 + cp*2 + 1];
                acc2[0] = f2(pa, w0.u.lo, acc2[0]);
                acc2[1] = f2(pa, w0.u.hi, acc2[1]);
                acc2[2] = f2(pa, w1.u.lo, acc2[2]);
                acc2[3] = f2(pa, w1.u.hi, acc2[3]);
            }
        }
        float2 r0_ = up2(acc2[0]), r1_ = up2(acc2[1]), r2_ = up2(acc2[2]), r3_ = up2(acc2[3]);
        ((float4*)out_edge)[(size_t)(e0 + r)*4 + cp*2]     = make_float4(r0_.x, r0_.y, r1_.x, r1_.y);
        ((float4*)out_edge)[(size_t)(e0 + r)*4 + cp*2 + 1] = make_float4(r2_.x, r2_.y, r3_.x, r3_.y);
    }
}

// ============ pass 2: exp weights, den, weighted value aggregation ============
__global__ void edge_attn(const int* __restrict__ ei) {
    int w = threadIdx.x >> 5, lane = threadIdx.x & 31;
    int e = blockIdx.x * 8 + w;
    int i = ei[e], j = ei[Ee + e];
    float ex = 0.f;
    if (lane < 4) {
        float s = g_scores[(size_t)e*4 + lane];
        float m = g_smax[i*4 + lane];
        ex = expf(s - m);
        atomicAdd(&g_den[i*4 + lane], ex);
    }
    float exh = __shfl_sync(0xffffffffu, ex, lane >> 3);
    float4 v4 = ((const float4*)g_val)[(size_t)j*32 + lane];
    float* base = &g_numer[(size_t)i*128 + lane*4];
    asm volatile("red.global.add.v4.f32 [%0], {%1,%2,%3,%4};"
                 :: "l"(base), "f"(exh*v4.x), "f"(exh*v4.y), "f"(exh*v4.z), "f"(exh*v4.w)
                 : "memory");
}

// ---------------- GraphNorm apply (output pass), float4-vectorized ----------------
__global__ void k_norm4(const float* __restrict__ w_, const float* __restrict__ b_,
                        const float* __restrict__ a_, const int* __restrict__ batch,
                        const float* __restrict__ X, float* __restrict__ Y, int statoff) {
    int idx = blockIdx.x*256 + threadIdx.x;
    if (idx >= Nn*32) return;
    int n = idx >> 5, q = idx & 31;
    int b = batch[n];
    float rc = 1.f / fmaxf(g_stats[4*Gg*Hh + b], 1.f);
    float4 s1 = *(const float4*)&g_stats[statoff + b*Hh + q*4];
    float4 s2 = *(const float4*)&g_stats[statoff + Gg*Hh + b*Hh + q*4];
    float4 x = ((const float4*)X)[(size_t)n*32 + q];
    float4 y = gnorm4(x, s1, s2, rc,
                      ((const float4*)a_)[q], ((const float4*)w_)[q], ((const float4*)b_)[q]);
    ((float4*)Y)[(size_t)n*32 + q] = y;
}

// ---------------- launch ----------------
extern "C" void kernel_launch(void* const* d_in, const int* in_sizes, int n_in,
                              void* d_out, int out_size) {
    const float* node = (const float*)d_in[0];
    const float* edge = (const float*)d_in[1];
    const float* coords = (const float*)d_in[2];
    const float* Ws = (const float*)d_in[3];  const float* bs = (const float*)d_in[4];
    const float* Wd = (const float*)d_in[5];  const float* bd = (const float*)d_in[6];
    const float* Wv = (const float*)d_in[7];  const float* bv = (const float*)d_in[8];
    const float* We1 = (const float*)d_in[9]; const float* be1 = (const float*)d_in[10];
    const float* We2 = (const float*)d_in[11];const float* be2 = (const float*)d_in[12];
    const float* Wun = (const float*)d_in[13];const float* bun = (const float*)d_in[14];
    const float* Wue = (const float*)d_in[15];const float* bue = (const float*)d_in[16];
    const float* Wg  = (const float*)d_in[17];const float* bg  = (const float*)d_in[18];
    const float* Wf1 = (const float*)d_in[19];const float* bf1 = (const float*)d_in[20];
    const float* Wf2 = (const float*)d_in[21];const float* bf2 = (const float*)d_in[22];
    const float* gn1w = (const float*)d_in[23];
    const float* gn1b = (const float*)d_in[24];
    const float* gn1a = (const float*)d_in[25];
    const float* gn2w = (const float*)d_in[26];
    const float* gn2b = (const float*)d_in[27];
    const float* gn2a = (const float*)d_in[28];
    const int* ei = (const int*)d_in[29];
    const int* batch = (const int*)d_in[30];

    float* out = (float*)d_out;
    float* out_n2 = out;
    float* out_edge = out + (size_t)Nn*Hh;
    float* out_coords = out + (size_t)Nn*Hh + (size_t)Ee*16;

    size_t gemm_smem = (8192 + 128*132) * sizeof(float);                         // 100352
    size_t ef_smem   = (8448 + 16896 + 512 + 128 + 128 + 16) * sizeof(float)
                     + 256 * sizeof(int);                                         // 105536
    cudaFuncSetAttribute(gemm_proj,    cudaFuncAttributeMaxDynamicSharedMemorySize, (int)gemm_smem);
    cudaFuncSetAttribute(gemm_nngate,  cudaFuncAttributeMaxDynamicSharedMemorySize, (int)gemm_smem);
    cudaFuncSetAttribute(gemm_fix_h2,  cudaFuncAttributeMaxDynamicSharedMemorySize, (int)gemm_smem);
    cudaFuncSetAttribute(edge_fused,   cudaFuncAttributeMaxDynamicSharedMemorySize, (int)ef_smem);

    float *p_src,*p_dst,*p_val,*p_h2;
    void* p;
    cudaGetSymbolAddress(&p, g_src); p_src = (float*)p;
    cudaGetSymbolAddress(&p, g_dst); p_dst = (float*)p;
    cudaGetSymbolAddress(&p, g_val); p_val = (float*)p;
    cudaGetSymbolAddress(&p, g_h2); p_h2 = (float*)p;

    cudaGetSymbolAddress(&p, g_smax);  cudaMemsetAsync(p, 0, sizeof(float)*Nn*NHh, 0);
    cudaGetSymbolAddress(&p, g_den);   cudaMemsetAsync(p, 0, sizeof(float)*Nn*NHh, 0);
    cudaGetSymbolAddress(&p, g_numer); cudaMemsetAsync(p, 0, sizeof(float)*Nn*Hh, 0);
    cudaGetSymbolAddress(&p, g_stats); cudaMemsetAsync(p, 0, sizeof(float)*(4*Gg*Hh + Gg), 0);

    int vecGrid  = (Nn*32 + 255) / 256;     // 3750
    int edgeWGrid = Ee / 8;                 // 60000
    int edgeFGrid = Ee / 128;               // 3750

    // node projections + gate-part: 4*NTILES independent (tile, weight) tasks
    gemm_proj<<<4*NTILES, 256, gemm_smem>>>(node, Ws, bs, p_src, Wd, bd, p_dst,
                                            Wv, bv, p_val, Wg, bg);

    // fused edge pipeline (GEMM2 on tensor cores, tf32)
    edge_fused<<<edgeFGrid, 256, ef_smem>>>(edge, coords, We1, be1, We2, be2,
                                            Wue, bue, ei, out_edge);

    // softmax + aggregation
    edge_attn<<<edgeWGrid, 256>>>(ei);

    // merged: nodenew GEMM + gate (1 GEMM + precomputed gpart) + h1 + stats1
    gemm_nngate<<<NTILES, 256, gemm_smem>>>(node, Wun, bun, Wg, batch);

    // fix_node with inline norm1 + h2 + stats2
    gemm_fix_h2<<<NTILES, 256, gemm_smem>>>(Wf1, bf1, Wf2, bf2, gn1w, gn1b, gn1a, batch);

    // norm2 -> output
    k_norm4<<<vecGrid, 256>>>(gn2w, gn2b, gn2a, batch, p_h2, out_n2, 2*Gg*Hh);

    // coords pass-through
    cudaMemcpyAsync(out_coords, coords, sizeof(float)*Nn*3, cudaMemcpyDeviceToDevice, 0);

    (void)in_sizes; (void)n_in; (void)out_size;
}